// round 15
// baseline (speedup 1.0000x reference)
#include <cuda_runtime.h>
#include <cuda_fp16.h>
#include <math.h>
#include <stdint.h>

#define NN 50000
#define EE 1000000
#define NIN 1281
#define K1PAD 1312
#define HH 256
#define LL 4
#define KPAD 288            // 256 Hsum + 3 sh + 16 radial + 1 deg + 12 zero pad

// ---------------- scratch ----------------
__device__ float g_h[NN * HH];
__device__ float g_h2[NN * HH];
__device__ __align__(256) __half g_hh[NN * HH];
__device__ __align__(256) __half g_hh2[NN * HH];
__device__ __align__(256) __half g_Abufh[NN * KPAD];
__device__ float g_gate[NN];
__device__ int   g_deg[NN];
__device__ int   g_rowptr[NN + 1];
__device__ int   g_cursor[NN];
__device__ int   g_csrc[EE];
__device__ __align__(256) __half g_W1th[HH * K1PAD];
__device__ __align__(256) __half g_W2th[HH * HH];
__device__ __align__(256) __half g_pgW1th[64 * HH];
__device__ __align__(256) __half g_Wpackh[LL * HH * KPAD];
__device__ float g_scal[4];
__device__ float g_Gvec[HH];
__device__ int   g_bsum[64];
__device__ unsigned g_amax;

// ---------------- helpers ----------------
__device__ __forceinline__ float warp_sum(float v) {
    #pragma unroll
    for (int o = 16; o; o >>= 1) v += __shfl_xor_sync(0xffffffffu, v, o);
    return v;
}
__device__ __forceinline__ float silu_f(float x) { return x / (1.f + expf(-x)); }
__device__ __forceinline__ uint32_t smem_u32(const void* p) {
    uint32_t a;
    asm("{ .reg .u64 t; cvta.to.shared.u64 t, %1; cvt.u32.u64 %0, t; }" : "=r"(a) : "l"(p));
    return a;
}
__device__ __forceinline__ unsigned fkey(float f) {
    unsigned u = __float_as_uint(f);
    return (u & 0x80000000u) ? ~u : (u | 0x80000000u);
}
__device__ __forceinline__ float funkey(unsigned k) {
    unsigned u = (k & 0x80000000u) ? (k & 0x7fffffffu) : ~k;
    return __uint_as_float(u);
}
#define CP_ASYNC16(dst, src) \
    asm volatile("cp.async.ca.shared.global [%0], [%1], 16;" :: "r"(dst), "l"(src))
#define CP_COMMIT() asm volatile("cp.async.commit_group;" ::: "memory")
#define CP_WAIT1()  asm volatile("cp.async.wait_group 1;" ::: "memory")
#define CP_WAIT0()  asm volatile("cp.async.wait_group 0;" ::: "memory")

__device__ __forceinline__ void addh8(float* a, uint4 v) {
    __half2 h0 = *reinterpret_cast<__half2*>(&v.x);
    __half2 h1 = *reinterpret_cast<__half2*>(&v.y);
    __half2 h2 = *reinterpret_cast<__half2*>(&v.z);
    __half2 h3 = *reinterpret_cast<__half2*>(&v.w);
    float2 f0 = __half22float2(h0);
    float2 f1 = __half22float2(h1);
    float2 f2 = __half22float2(h2);
    float2 f3 = __half22float2(h3);
    a[0] += f0.x; a[1] += f0.y; a[2] += f1.x; a[3] += f1.y;
    a[4] += f2.x; a[5] += f2.y; a[6] += f3.x; a[7] += f3.y;
}

__device__ __forceinline__ uint4 pack8h(const float* v) {
    uint4 r;
    __half2 h0 = __floats2half2_rn(v[0], v[1]);
    __half2 h1 = __floats2half2_rn(v[2], v[3]);
    __half2 h2 = __floats2half2_rn(v[4], v[5]);
    __half2 h3 = __floats2half2_rn(v[6], v[7]);
    r.x = *reinterpret_cast<unsigned*>(&h0);
    r.y = *reinterpret_cast<unsigned*>(&h1);
    r.z = *reinterpret_cast<unsigned*>(&h2);
    r.w = *reinterpret_cast<unsigned*>(&h3);
    return r;
}

// ---------------- setup ----------------
__global__ void zero_kernel() {
    int i = blockIdx.x * 256 + threadIdx.x;
    if (i < NN) { g_deg[i] = 0; g_cursor[i] = 0; }
    if (i < HH) g_Gvec[i] = 0.f;
    if (i < 4) g_scal[i] = 0.f;
    if (i == 0) { g_rowptr[0] = 0; g_amax = 0u; }
}

__global__ void edge1_kernel(const int* __restrict__ ei) {
    int e = blockIdx.x * 256 + threadIdx.x;
    if (e >= EE) return;
    atomicAdd(&g_deg[ei[EE + e]], 1);
}

__global__ void scan1_kernel() {
    __shared__ int s[1024];
    int tid = threadIdx.x;
    int gid = blockIdx.x * 1024 + tid;
    int v = (gid < NN) ? g_deg[gid] : 0;
    s[tid] = v;
    __syncthreads();
    for (int off = 1; off < 1024; off <<= 1) {
        int t = (tid >= off) ? s[tid - off] : 0;
        __syncthreads();
        s[tid] += t;
        __syncthreads();
    }
    if (gid < NN) g_rowptr[gid + 1] = s[tid];
    if (tid == 1023) g_bsum[blockIdx.x] = s[1023];
}

__global__ void scan3b_kernel(int nb) {
    __shared__ int pref[64];
    int tid = threadIdx.x;
    if (tid < 64) pref[tid] = (tid < nb) ? g_bsum[tid] : 0;
    __syncthreads();
    for (int off = 1; off < 64; off <<= 1) {
        int t = (tid >= off && tid < 64) ? pref[tid - off] : 0;
        __syncthreads();
        if (tid < 64) pref[tid] += t;
        __syncthreads();
    }
    int gid = blockIdx.x * 256 + tid;
    if (gid < NN) {
        int b = gid >> 10;
        if (b > 0) g_rowptr[gid + 1] += pref[b - 1];
    }
}

__global__ void edge2_kernel(const int* __restrict__ ei) {
    int e = blockIdx.x * 256 + threadIdx.x;
    if (e >= EE) return;
    int s = ei[e];
    int d = ei[EE + e];
    int slot = atomicAdd(&g_cursor[d], 1);
    g_csrc[g_rowptr[d] + slot] = s;
}

// warp-per-node edge-feature aggregation
__global__ void ef_kernel(const float* __restrict__ pos) {
    int w = (blockIdx.x * 256 + threadIdx.x) >> 5;
    int lane = threadIdx.x & 31;
    if (w >= NN) return;
    const float wd = 0.1953125f;
    const float cstep = 10.f / 15.f;
    float Ej[16];
    #pragma unroll
    for (int j = 0; j < 16; j++) {
        float c = cstep * (float)j;
        Ej[j] = expf(-wd * c * c);
    }
    float px = pos[3 * w + 0], py = pos[3 * w + 1], pz = pos[3 * w + 2];
    float shx = 0.f, shy = 0.f, shz = 0.f;
    float rad[16];
    #pragma unroll
    for (int j = 0; j < 16; j++) rad[j] = 0.f;
    int beg = g_rowptr[w], end = g_rowptr[w + 1];
    for (int e = beg + lane; e < end; e += 32) {
        int s = g_csrc[e];
        float rx = px - pos[3 * s + 0];
        float ry = py - pos[3 * s + 1];
        float rz = pz - pos[3 * s + 2];
        float dist = sqrtf(rx * rx + ry * ry + rz * rz);
        float inv = 1.f / fmaxf(dist, 1e-12f);
        shx += rx * inv; shy += ry * inv; shz += rz * inv;
        if (dist < 18.f) {
            float A = expf(-wd * dist * dist);
            float r1 = expf(2.f * wd * cstep * dist);
            float r2 = r1 * r1, r4 = r2 * r2, r8 = r4 * r4;
            float p[16];
            p[0] = A;         p[1] = A * r1;
            p[2] = p[0] * r2; p[3] = p[1] * r2;
            #pragma unroll
            for (int j = 0; j < 4; j++) p[4 + j] = p[j] * r4;
            #pragma unroll
            for (int j = 0; j < 8; j++) p[8 + j] = p[j] * r8;
            #pragma unroll
            for (int j = 0; j < 16; j++) rad[j] += p[j] * Ej[j];
        } else {
            #pragma unroll
            for (int j = 0; j < 16; j++) {
                float t = dist - cstep * (float)j;
                rad[j] += expf(-wd * t * t);
            }
        }
    }
    shx = warp_sum(shx);
    shy = warp_sum(shy);
    shz = warp_sum(shz);
    #pragma unroll
    for (int j = 0; j < 16; j++) rad[j] = warp_sum(rad[j]);
    if (lane == 0) {
        __half* ab = g_Abufh + (long)w * KPAD + 256;
        ab[0] = __float2half_rn(shx);
        ab[1] = __float2half_rn(shy);
        ab[2] = __float2half_rn(shz);
        #pragma unroll
        for (int j = 0; j < 16; j++) ab[3 + j] = __float2half_rn(rad[j]);
        ab[19] = __float2half_rn((float)(end - beg));
        #pragma unroll
        for (int j = 20; j < 32; j++) ab[j] = __float2half_rn(0.f);
    }
}

// merged weight preparation
#define PREP_S1 ((long)HH * K1PAD)
#define PREP_S2 (PREP_S1 + (long)HH * HH)
#define PREP_S3 (PREP_S2 + 64L * HH)
#define PREP_S4 (PREP_S3 + (long)LL * HH * KPAD)
__global__ void prep_kernel(const float* __restrict__ ne_W1, const float* __restrict__ ne_W2,
                            const float* __restrict__ pgW1,
                            const float* __restrict__ convW, const float* __restrict__ convB) {
    long idx = (long)blockIdx.x * 256 + threadIdx.x;
    if (idx < PREP_S1) {
        int n = (int)(idx / K1PAD), k = (int)(idx % K1PAD);
        g_W1th[idx] = __float2half_rn((k < NIN) ? ne_W1[(long)k * HH + n] : 0.f);
    } else if (idx < PREP_S2) {
        long r = idx - PREP_S1;
        int n = (int)(r / HH), k = (int)(r % HH);
        g_W2th[r] = __float2half_rn(ne_W2[(long)k * HH + n]);
    } else if (idx < PREP_S3) {
        long r = idx - PREP_S2;
        int n = (int)(r / HH), k = (int)(r % HH);
        g_pgW1th[r] = __float2half_rn(pgW1[(long)k * 64 + n]);
    } else if (idx < PREP_S4) {
        long r = idx - PREP_S3;
        int l = (int)(r / (HH * KPAD));
        int rem = (int)(r % (HH * KPAD));
        int n = rem / KPAD, k = rem % KPAD;
        float v = 0.f;
        if (k < 275)       v = convW[((long)l * 275 + k) * HH + n];
        else if (k == 275) v = convB[l * HH + n];
        g_Wpackh[r] = __float2half_rn(v);
    }
}

// ---------------- shared GEMM constants ----------------
#define ASTH 40
#define STGH ((128 + 256) * ASTH)
#define EPI_ST 258
#define HG_DSM (128 * EPI_ST * 4)

// ================= fused node encoder: 1024 threads, warp tile 32x32 =================
#define AT2_ST 264
#define B2_STG (256 * ASTH)
__global__ __launch_bounds__(1024, 1)
void encoder_fused_kernel(const float* __restrict__ x,
                          const __half* __restrict__ W1t,
                          const float* __restrict__ b1,
                          const __half* __restrict__ W2t,
                          const float* __restrict__ b2,
                          const float* __restrict__ lnG, const float* __restrict__ lnB,
                          float* __restrict__ houtF, __half* __restrict__ houtH) {
    extern __shared__ float smf[];
    __half* sm = (__half*)smf;
    int t = threadIdx.x;
    int lane = t & 31, warp = t >> 5;     // 32 warps
    int wr = warp >> 3;                   // 0..3 (32-row bands)
    int wc = warp & 7;                    // 0..7 (32-col bands)
    int rowBase = blockIdx.x * 128;
    uint32_t smb = smem_u32(sm);

    int aRow = t >> 2, aCq = t & 3;       // A staging: threads 0..511
    int aGr = rowBase + ((aRow < 128) ? aRow : 127);
    if (aGr >= NN) aGr = NN - 1;

    int kq = lane & 3;
    int kg = lane >> 2;

    float acc[2][4][4];
    #pragma unroll
    for (int mi = 0; mi < 2; mi++)
        #pragma unroll
        for (int ni = 0; ni < 4; ni++)
            #pragma unroll
            for (int q = 0; q < 4; q++) acc[mi][ni][q] = 0.f;

    // ---------- phase 1: K = NIN ----------
    {
        const int K = NIN;
        int nT = (K + 31) >> 5;
        auto load_B = [&](int i, int s) {
            int k0 = i << 5;
            uint32_t sbase = smb + (uint32_t)(s * STGH) * 2u;
            int n = t >> 2, cq = t & 3;   // 256 rows x 4 chunks = 1024
            const __half* src = W1t + (long)n * K1PAD + k0 + cq * 8;
            uint32_t dst = sbase + (uint32_t)(128 * ASTH + n * ASTH + cq * 8) * 2u;
            CP_ASYNC16(dst, src);
        };
        auto ldg_A = [&](int i, float* r) {
            if (t >= 512) return;
            int k0 = (i << 5) + aCq * 8;
            const float* src = x + (long)aGr * NIN + k0;
            #pragma unroll
            for (int j = 0; j < 8; j++)
                r[j] = (k0 + j < K) ? src[j] : 0.f;
        };
        auto sts_A = [&](int s, const float* r) {
            if (t >= 512) return;
            __half* dst = sm + s * STGH + aRow * ASTH + aCq * 8;
            *(uint4*)dst = pack8h(r);
        };

        {
            float r0[8];
            ldg_A(0, r0); sts_A(0, r0);
            ldg_A(1, r0); sts_A(1, r0);
        }
        load_B(0, 0);
        CP_COMMIT();
        load_B(1, 1);
        CP_COMMIT();

        for (int i = 0; i < nT; i++) {
            CP_WAIT1();
            __syncthreads();
            float aStage[8];
            bool doStage = (i + 2 < nT);
            if (doStage) {
                ldg_A(i + 2, aStage);
                load_B(i + 2, (i + 2) % 3);
            }
            CP_COMMIT();

            const __half* As = sm + (i % 3) * STGH;
            const __half* Bs = As + 128 * ASTH;
            #pragma unroll
            for (int ks = 0; ks < 2; ks++) {
                int ko = ks * 16;
                unsigned af[2][4], bf[4][2];
                #pragma unroll
                for (int mi = 0; mi < 2; mi++) {
                    int ar = wr * 32 + mi * 16 + kg;
                    af[mi][0] = *(const unsigned*)(As + ar * ASTH + ko + kq * 2);
                    af[mi][1] = *(const unsigned*)(As + (ar + 8) * ASTH + ko + kq * 2);
                    af[mi][2] = *(const unsigned*)(As + ar * ASTH + ko + kq * 2 + 8);
                    af[mi][3] = *(const unsigned*)(As + (ar + 8) * ASTH + ko + kq * 2 + 8);
                }
                #pragma unroll
                for (int ni = 0; ni < 4; ni++) {
                    int bn = wc * 32 + ni * 8 + kg;
                    bf[ni][0] = *(const unsigned*)(Bs + bn * ASTH + ko + kq * 2);
                    bf[ni][1] = *(const unsigned*)(Bs + bn * ASTH + ko + kq * 2 + 8);
                }
                #pragma unroll
                for (int mi = 0; mi < 2; mi++)
                    #pragma unroll
                    for (int ni = 0; ni < 4; ni++) {
                        asm volatile(
                            "mma.sync.aligned.m16n8k16.row.col.f32.f16.f16.f32 "
                            "{%0,%1,%2,%3}, {%4,%5,%6,%7}, {%8,%9}, {%0,%1,%2,%3};"
                            : "+f"(acc[mi][ni][0]), "+f"(acc[mi][ni][1]),
                              "+f"(acc[mi][ni][2]), "+f"(acc[mi][ni][3])
                            : "r"(af[mi][0]), "r"(af[mi][1]), "r"(af[mi][2]), "r"(af[mi][3]),
                              "r"(bf[ni][0]), "r"(bf[ni][1]));
                    }
            }
            if (doStage) sts_A((i + 2) % 3, aStage);
        }
    }

    // ---------- phase boundary: t1 tile = silu(acc + b1) -> smem half [128][AT2_ST] -------
    CP_WAIT0();
    __syncthreads();
    #pragma unroll
    for (int mi = 0; mi < 2; mi++) {
        #pragma unroll
        for (int ni = 0; ni < 4; ni++) {
            int rloc0 = wr * 32 + mi * 16 + kg;
            int c0 = wc * 32 + ni * 8 + kq * 2;
            #pragma unroll
            for (int half = 0; half < 2; half++) {
                int rl = rloc0 + half * 8;
                float v0 = silu_f(acc[mi][ni][half * 2 + 0] + b1[c0]);
                float v1 = silu_f(acc[mi][ni][half * 2 + 1] + b1[c0 + 1]);
                *(__half2*)(sm + rl * AT2_ST + c0) = __floats2half2_rn(v0, v1);
            }
        }
    }
    __syncthreads();

    #pragma unroll
    for (int mi = 0; mi < 2; mi++)
        #pragma unroll
        for (int ni = 0; ni < 4; ni++)
            #pragma unroll
            for (int q = 0; q < 4; q++) acc[mi][ni][q] = 0.f;

    // ---------- phase 2: K = 256, A persistent, B = W2t streamed ----------
    {
        const __half* At = sm;
        __half* B2 = sm + 128 * AT2_ST;
        uint32_t b2b = smem_u32(B2);
        auto load_B2 = [&](int i, int s) {
            int k0 = i << 5;
            uint32_t sbase = b2b + (uint32_t)(s * B2_STG) * 2u;
            int n = t >> 2, cq = t & 3;
            const __half* src = W2t + (long)n * HH + k0 + cq * 8;
            uint32_t dst = sbase + (uint32_t)(n * ASTH + cq * 8) * 2u;
            CP_ASYNC16(dst, src);
        };
        load_B2(0, 0);
        CP_COMMIT();
        load_B2(1, 1);
        CP_COMMIT();
        for (int i = 0; i < 8; i++) {
            CP_WAIT1();
            __syncthreads();
            if (i + 2 < 8) load_B2(i + 2, (i + 2) % 3);
            CP_COMMIT();
            int k0 = i << 5;
            const __half* Bs = B2 + (i % 3) * B2_STG;
            #pragma unroll
            for (int ks = 0; ks < 2; ks++) {
                int ko = ks * 16;
                unsigned af[2][4], bf[4][2];
                #pragma unroll
                for (int mi = 0; mi < 2; mi++) {
                    int ar = wr * 32 + mi * 16 + kg;
                    af[mi][0] = *(const unsigned*)(At + ar * AT2_ST + k0 + ko + kq * 2);
                    af[mi][1] = *(const unsigned*)(At + (ar + 8) * AT2_ST + k0 + ko + kq * 2);
                    af[mi][2] = *(const unsigned*)(At + ar * AT2_ST + k0 + ko + kq * 2 + 8);
                    af[mi][3] = *(const unsigned*)(At + (ar + 8) * AT2_ST + k0 + ko + kq * 2 + 8);
                }
                #pragma unroll
                for (int ni = 0; ni < 4; ni++) {
                    int bn = wc * 32 + ni * 8 + kg;
                    bf[ni][0] = *(const unsigned*)(Bs + bn * ASTH + ko + kq * 2);
                    bf[ni][1] = *(const unsigned*)(Bs + bn * ASTH + ko + kq * 2 + 8);
                }
                #pragma unroll
                for (int mi = 0; mi < 2; mi++)
                    #pragma unroll
                    for (int ni = 0; ni < 4; ni++) {
                        asm volatile(
                            "mma.sync.aligned.m16n8k16.row.col.f32.f16.f16.f32 "
                            "{%0,%1,%2,%3}, {%4,%5,%6,%7}, {%8,%9}, {%0,%1,%2,%3};"
                            : "+f"(acc[mi][ni][0]), "+f"(acc[mi][ni][1]),
                              "+f"(acc[mi][ni][2]), "+f"(acc[mi][ni][3])
                            : "r"(af[mi][0]), "r"(af[mi][1]), "r"(af[mi][2]), "r"(af[mi][3]),
                              "r"(bf[ni][0]), "r"(bf[ni][1]));
                    }
            }
        }
    }

    // ---------- LN epilogue ----------
    CP_WAIT0();
    __syncthreads();
    #pragma unroll
    for (int mi = 0; mi < 2; mi++) {
        #pragma unroll
        for (int ni = 0; ni < 4; ni++) {
            int rloc0 = wr * 32 + mi * 16 + kg;
            int c0 = wc * 32 + ni * 8 + kq * 2;
            #pragma unroll
            for (int half = 0; half < 2; half++) {
                int rl = rloc0 + half * 8;
                #pragma unroll
                for (int q = 0; q < 2; q++) {
                    int c = c0 + q;
                    smf[rl * EPI_ST + c] = acc[mi][ni][half * 2 + q] + b2[c];
                }
            }
        }
    }
    __syncthreads();
    #pragma unroll
    for (int rr = 0; rr < 4; rr++) {
        int rl = rr * 32 + warp;
        int gr = rowBase + rl;
        if (gr >= NN) continue;
        float xv[8];
        #pragma unroll
        for (int i = 0; i < 8; i++) xv[i] = smf[rl * EPI_ST + lane + 32 * i];
        float s = 0.f;
        #pragma unroll
        for (int i = 0; i < 8; i++) s += xv[i];
        s = warp_sum(s);
        float m = s * (1.f / 256.f);
        float qv = 0.f;
        #pragma unroll
        for (int i = 0; i < 8; i++) { float d = xv[i] - m; qv += d * d; }
        qv = warp_sum(qv);
        float rs = rsqrtf(qv * (1.f / 256.f) + 1e-5f);
        float* of = houtF + (long)gr * HH;
        __half* oh = houtH + (long)gr * HH;
        #pragma unroll
        for (int i = 0; i < 8; i++) {
            int c = lane + 32 * i;
            float y = (xv[i] - m) * rs * lnG[c] + lnB[c];
            of[c] = y;
            oh[c] = __float2half_rn(y);
        }
    }
}

// ================= FP16 GEMM (conv layers): 1024 threads, warp tile 32x32 ======
__global__ __launch_bounds__(1024, 1)
void hgemm_kernel(const __half* __restrict__ A, int lda, int M, int K,
                  const __half* __restrict__ Bt, int ldb,
                  const float* __restrict__ p1, const float* __restrict__ p2,
                  const float* __restrict__ p3, const float* __restrict__ p4,
                  const float* __restrict__ hinF,
                  float* __restrict__ houtF, __half* __restrict__ houtH) {
    extern __shared__ float smf[];
    __half* sm = (__half*)smf;
    int t = threadIdx.x;
    int lane = t & 31, warp = t >> 5;
    int wr = warp >> 3;
    int wc = warp & 7;
    int rowBase = blockIdx.x * 128;
    uint32_t smb = smem_u32(sm);

    int nT = (K + 31) >> 5;
    int aRow = t >> 2, aCq = t & 3;
    int aGr = rowBase + ((aRow < 128) ? aRow : 127);
    if (aGr >= M) aGr = M - 1;

    float acc[2][4][4];
    #pragma unroll
    for (int mi = 0; mi < 2; mi++)
        #pragma unroll
        for (int ni = 0; ni < 4; ni++)
            #pragma unroll
            for (int q = 0; q < 4; q++) acc[mi][ni][q] = 0.f;

    auto load_stage = [&](int i, int s) {
        int k0 = i << 5;
        uint32_t sbase = smb + (uint32_t)(s * STGH) * 2u;
        if (t < 512) {
            const __half* src = A + (long)aGr * lda + k0 + aCq * 8;
            uint32_t dst = sbase + (uint32_t)(aRow * ASTH + aCq * 8) * 2u;
            CP_ASYNC16(dst, src);
        }
        {
            int n = t >> 2, cq = t & 3;
            const __half* src = Bt + (long)n * ldb + k0 + cq * 8;
            uint32_t dst = sbase + (uint32_t)(128 * ASTH + n * ASTH + cq * 8) * 2u;
            CP_ASYNC16(dst, src);
        }
    };

    load_stage(0, 0);
    CP_COMMIT();
    if (nT > 1) load_stage(1, 1);
    CP_COMMIT();

    int kq = lane & 3;
    int kg = lane >> 2;

    for (int i = 0; i < nT; i++) {
        CP_WAIT1();
        __syncthreads();
        if (i + 2 < nT) load_stage(i + 2, (i + 2) % 3);
        CP_COMMIT();

        const __half* As = sm + (i % 3) * STGH;
        const __half* Bs = As + 128 * ASTH;
        #pragma unroll
        for (int ks = 0; ks < 2; ks++) {
            int ko = ks * 16;
            unsigned af[2][4], bf[4][2];
            #pragma unroll
            for (int mi = 0; mi < 2; mi++) {
                int ar = wr * 32 + mi * 16 + kg;
                af[mi][0] = *(const unsigned*)(As + ar * ASTH + ko + kq * 2);
                af[mi][1] = *(const unsigned*)(As + (ar + 8) * ASTH + ko + kq * 2);
                af[mi][2] = *(const unsigned*)(As + ar * ASTH + ko + kq * 2 + 8);
                af[mi][3] = *(const unsigned*)(As + (ar + 8) * ASTH + ko + kq * 2 + 8);
            }
            #pragma unroll
            for (int ni = 0; ni < 4; ni++) {
                int bn = wc * 32 + ni * 8 + kg;
                bf[ni][0] = *(const unsigned*)(Bs + bn * ASTH + ko + kq * 2);
                bf[ni][1] = *(const unsigned*)(Bs + bn * ASTH + ko + kq * 2 + 8);
            }
            #pragma unroll
            for (int mi = 0; mi < 2; mi++)
                #pragma unroll
                for (int ni = 0; ni < 4; ni++) {
                    asm volatile(
                        "mma.sync.aligned.m16n8k16.row.col.f32.f16.f16.f32 "
                        "{%0,%1,%2,%3}, {%4,%5,%6,%7}, {%8,%9}, {%0,%1,%2,%3};"
                        : "+f"(acc[mi][ni][0]), "+f"(acc[mi][ni][1]),
                          "+f"(acc[mi][ni][2]), "+f"(acc[mi][ni][3])
                        : "r"(af[mi][0]), "r"(af[mi][1]), "r"(af[mi][2]), "r"(af[mi][3]),
                          "r"(bf[ni][0]), "r"(bf[ni][1]));
                }
        }
    }

    // postconv epilogue
    __syncthreads();
    #pragma unroll
    for (int mi = 0; mi < 2; mi++) {
        #pragma unroll
        for (int ni = 0; ni < 4; ni++) {
            int rloc0 = wr * 32 + mi * 16 + kg;
            int c0 = wc * 32 + ni * 8 + kq * 2;
            #pragma unroll
            for (int half = 0; half < 2; half++) {
                int rl = rloc0 + half * 8;
                #pragma unroll
                for (int q = 0; q < 2; q++) {
                    int c = c0 + q;
                    smf[rl * EPI_ST + c] = acc[mi][ni][half * 2 + q];
                }
            }
        }
    }
    __syncthreads();

    #pragma unroll
    for (int rr = 0; rr < 4; rr++) {
        int rl = rr * 32 + warp;
        int gr = rowBase + rl;
        if (gr >= M) continue;
        const float* hp = hinF + (long)gr * HH;
        float* of = houtF + (long)gr * HH;
        __half* oh = houtH + (long)gr * HH;
        float x[8];
        float s = 0.f;
        #pragma unroll
        for (int i = 0; i < 8; i++) {
            x[i] = silu_f(smf[rl * EPI_ST + lane + 32 * i]);
            s += x[i];
        }
        s = warp_sum(s);
        float m1 = s * (1.f / 256.f);
        float qv = 0.f;
        #pragma unroll
        for (int i = 0; i < 8; i++) { float d = x[i] - m1; qv += d * d; }
        qv = warp_sum(qv);
        float rs1 = rsqrtf(qv * (1.f / 256.f) + 1e-5f);
        float z[8];
        float s2 = 0.f;
        #pragma unroll
        for (int i = 0; i < 8; i++) {
            int c = lane + 32 * i;
            float y = (x[i] - m1) * rs1 * p1[c] + p2[c];
            float zz = hp[c] + y;
            z[i] = zz; s2 += zz;
        }
        s2 = warp_sum(s2);
        float m2 = s2 * (1.f / 256.f);
        float q2 = 0.f;
        #pragma unroll
        for (int i = 0; i < 8; i++) { float d = z[i] - m2; q2 += d * d; }
        q2 = warp_sum(q2);
        float rs2 = rsqrtf(q2 * (1.f / 256.f) + 1e-5f);
        #pragma unroll
        for (int i = 0; i < 8; i++) {
            int c = lane + 32 * i;
            float y = (z[i] - m2) * rs2 * p3[c] + p4[c];
            of[c] = y;
            oh[c] = __float2half_rn(y);
        }
    }
}

// ---------------- gather (half source) ----------------
__global__ void gatherh_kernel(const __half* __restrict__ hinh) {
    int w = (blockIdx.x * 256 + threadIdx.x) >> 5;
    int lane = threadIdx.x & 31;
    if (w >= NN) return;
    float a[8], b[8];
    #pragma unroll
    for (int j = 0; j < 8; j++) { a[j] = 0.f; b[j] = 0.f; }
    const uint4* base = (const uint4*)hinh;
    int beg = g_rowptr[w], end = g_rowptr[w + 1];
    int e = beg;
    for (; e + 1 < end; e += 2) {
        int s0 = g_csrc[e], s1 = g_csrc[e + 1];
        uint4 v = base[(long)s0 * 32 + lane];
        uint4 u = base[(long)s1 * 32 + lane];
        addh8(a, v);
        addh8(b, u);
    }
    if (e < end) {
        uint4 v = base[(long)g_csrc[e] * 32 + lane];
        addh8(a, v);
    }
    float out[8];
    #pragma unroll
    for (int j = 0; j < 8; j++) out[j] = a[j] + b[j];
    *(uint4*)(g_Abufh + (long)w * KPAD + lane * 8) = pack8h(out);
}

// ================= pool gate GEMM (fp16) + fused gate dot + block max =================
#define PG_STG ((128 + 64) * ASTH)
#define PG_DSM (3 * PG_STG * 2)
__global__ __launch_bounds__(256, 2)
void pgate_kernel(const __half* __restrict__ hh, const __half* __restrict__ Bt,
                  const float* __restrict__ bias,
                  const float* __restrict__ pgW2, const float* __restrict__ pgb2) {
    extern __shared__ __half smh[];
    __shared__ float wmax[8];
    float* smf = (float*)smh;
    int t = threadIdx.x;
    int lane = t & 31, warp = t >> 5;
    int wr = warp >> 2;
    int wc = warp & 3;
    int rowBase = blockIdx.x * 128;
    uint32_t smb = smem_u32(smh);

    float acc[4][2][4];
    #pragma unroll
    for (int mi = 0; mi < 4; mi++)
        #pragma unroll
        for (int ni = 0; ni < 2; ni++)
            #pragma unroll
            for (int q = 0; q < 4; q++) acc[mi][ni][q] = 0.f;

    auto load_stage = [&](int i, int s) {
        int k0 = i << 5;
        uint32_t sbase = smb + (uint32_t)(s * PG_STG) * 2u;
        #pragma unroll
        for (int it = 0; it < 2; it++) {
            int c = it * 256 + t;
            int row = c >> 2, cq = c & 3;
            int gr = rowBase + row;
            if (gr >= NN) gr = NN - 1;
            const __half* src = hh + (long)gr * HH + k0 + cq * 8;
            uint32_t dst = sbase + (uint32_t)(row * ASTH + cq * 8) * 2u;
            CP_ASYNC16(dst, src);
        }
        {
            int n = t >> 2, cq = t & 3;
            const __half* src = Bt + (long)n * HH + k0 + cq * 8;
            uint32_t dst = sbase + (uint32_t)(128 * ASTH + n * ASTH + cq * 8) * 2u;
            CP_ASYNC16(dst, src);
        }
    };

    load_stage(0, 0);
    CP_COMMIT();
    load_stage(1, 1);
    CP_COMMIT();

    int kq = lane & 3;
    int kg = lane >> 2;

    for (int i = 0; i < 8; i++) {
        CP_WAIT1();
        __syncthreads();
        if (i + 2 < 8) load_stage(i + 2, (i + 2) % 3);
        CP_COMMIT();

        const __half* As = smh + (i % 3) * PG_STG;
        const __half* Bs = As + 128 * ASTH;
        #pragma unroll
        for (int ks = 0; ks < 2; ks++) {
            int ko = ks * 16;
            unsigned af[4][4], bf[2][2];
            #pragma unroll
            for (int mi = 0; mi < 4; mi++) {
                int ar = wr * 64 + mi * 16 + kg;
                af[mi][0] = *(const unsigned*)(As + ar * ASTH + ko + kq * 2);
                af[mi][1] = *(const unsigned*)(As + (ar + 8) * ASTH + ko + kq * 2);
                af[mi][2] = *(const unsigned*)(As + ar * ASTH + ko + kq * 2 + 8);
                af[mi][3] = *(const unsigned*)(As + (ar + 8) * ASTH + ko + kq * 2 + 8);
            }
            #pragma unroll
            for (int ni = 0; ni < 2; ni++) {
                int bn = wc * 16 + ni * 8 + kg;
                bf[ni][0] = *(const unsigned*)(Bs + bn * ASTH + ko + kq * 2);
                bf[ni][1] = *(const unsigned*)(Bs + bn * ASTH + ko + kq * 2 + 8);
            }
            #pragma unroll
            for (int mi = 0; mi < 4; mi++)
                #pragma unroll
                for (int ni = 0; ni < 2; ni++) {
                    asm volatile(
                        "mma.sync.aligned.m16n8k16.row.col.f32.f16.f16.f32 "
                        "{%0,%1,%2,%3}, {%4,%5,%6,%7}, {%8,%9}, {%0,%1,%2,%3};"
                        : "+f"(acc[mi][ni][0]), "+f"(acc[mi][ni][1]),
                          "+f"(acc[mi][ni][2]), "+f"(acc[mi][ni][3])
                        : "r"(af[mi][0]), "r"(af[mi][1]), "r"(af[mi][2]), "r"(af[mi][3]),
                          "r"(bf[ni][0]), "r"(bf[ni][1]));
                }
        }
    }

    CP_WAIT0();
    __syncthreads();
    #pragma unroll
    for (int mi = 0; mi < 4; mi++) {
        #pragma unroll
        for (int ni = 0; ni < 2; ni++) {
            int r0 = wr * 64 + mi * 16 + kg;
            int c0 = wc * 16 + ni * 8 + kq * 2;
            #pragma unroll
            for (int half = 0; half < 2; half++) {
                int rl = r0 + half * 8;
                #pragma unroll
                for (int q = 0; q < 2; q++) {
                    int c = c0 + q;
                    smf[rl * 64 + c] = silu_f(acc[mi][ni][half * 2 + q] + bias[c]);
                }
            }
        }
    }
    __syncthreads();
    float lmax = -1e30f;
    float w0 = pgW2[lane], w1 = pgW2[32 + lane];
    for (int rr = 0; rr < 16; rr++) {
        int rl = rr * 8 + warp;
        int gr = rowBase + rl;
        if (gr >= NN) continue;
        float v = smf[rl * 64 + lane] * w0 + smf[rl * 64 + 32 + lane] * w1;
        v = warp_sum(v);
        if (lane == 0) {
            float g = v + pgb2[0];
            g_gate[gr] = g;
            lmax = fmaxf(lmax, g);
        }
    }
    if (lane == 0) wmax[warp] = lmax;
    __syncthreads();
    if (t == 0) {
        float m = wmax[0];
        #pragma unroll
        for (int j = 1; j < 8; j++) m = fmaxf(m, wmax[j]);
        atomicMax(&g_amax, fkey(m));
    }
}

// ---------------- pooling tail ----------------
__global__ void expwsum_kernel() {
    __shared__ float e[256];
    __shared__ float red[256];
    int tid = threadIdx.x;
    int n = blockIdx.x * 256 + tid;
    float M = funkey(g_amax);
    float ev = 0.f;
    if (n < NN) ev = expf(g_gate[n] - M);
    e[tid] = ev;
    red[tid] = ev;
    __syncthreads();
    for (int o = 128; o; o >>= 1) {
        if (tid < o) red[tid] += red[tid + o];
        __syncthreads();
    }
    if (tid == 0) atomicAdd(&g_scal[1], red[0]);
    float acc = 0.f;
    int n0 = blockIdx.x * 256;
    for (int i = 0; i < 256; i++) {
        int nn = n0 + i;
        if (nn >= NN) break;
        acc += e[i] * g_h[(long)nn * HH + tid];
    }
    atomicAdd(&g_Gvec[tid], acc);
}

// ---------------- heads ----------------
__global__ void heads_kernel(const float* __restrict__ clW1, const float* __restrict__ clb1,
                             const float* __restrict__ clW2, const float* __restrict__ clb2,
                             const float* __restrict__ prW1, const float* __restrict__ prb1,
                             const float* __restrict__ prW2, const float* __restrict__ prb2,
                             float* __restrict__ out) {
    __shared__ float emb[256], c1[128], p1[256], pr[128];
    __shared__ float nrm;
    int t = threadIdx.x;
    float se = g_scal[1];
    float ev = g_Gvec[t] / se;
    emb[t] = ev;
    out[132 + t] = ev;
    __syncthreads();
    if (t < 128) {
        float a = 0.f;
        for (int k = 0; k < 256; k++) a += emb[k] * clW1[k * 128 + t];
        a += clb1[t];
        c1[t] = silu_f(a);
    }
    {
        float a = 0.f;
        for (int k = 0; k < 256; k++) a += emb[k] * prW1[k * 256 + t];
        a += prb1[t];
        p1[t] = silu_f(a);
    }
    __syncthreads();
    if (t < 4) {
        float a = 0.f;
        for (int k = 0; k < 128; k++) a += c1[k] * clW2[k * 4 + t];
        out[t] = a + clb2[t];
    }
    if (t < 128) {
        float a = 0.f;
        for (int k = 0; k < 256; k++) a += p1[k] * prW2[k * 128 + t];
        pr[t] = a + prb2[t];
    }
    __syncthreads();
    if (t == 0) {
        float s = 0.f;
        for (int k = 0; k < 128; k++) s += pr[k] * pr[k];
        nrm = fmaxf(sqrtf(s), 1e-12f);
    }
    __syncthreads();
    if (t < 128) out[4 + t] = pr[t] / nrm;
}

// ---------------- launch ----------------
extern "C" void kernel_launch(void* const* d_in, const int* in_sizes, int n_in,
                              void* d_out, int out_size) {
    const float* x       = (const float*)d_in[0];
    const float* pos     = (const float*)d_in[1];
    const int*   ei      = (const int*)d_in[2];
    const float* ne_W1   = (const float*)d_in[3];
    const float* ne_b1   = (const float*)d_in[4];
    const float* ne_W2   = (const float*)d_in[5];
    const float* ne_b2   = (const float*)d_in[6];
    const float* ne_g    = (const float*)d_in[7];
    const float* ne_beta = (const float*)d_in[8];
    const float* convW   = (const float*)d_in[9];
    const float* convB   = (const float*)d_in[10];
    const float* convG   = (const float*)d_in[11];
    const float* convBeta= (const float*)d_in[12];
    const float* lnG     = (const float*)d_in[13];
    const float* lnB     = (const float*)d_in[14];
    const float* pgW1    = (const float*)d_in[15];
    const float* pgb1    = (const float*)d_in[16];
    const float* pgW2    = (const float*)d_in[17];
    const float* pgb2    = (const float*)d_in[18];
    const float* clW1    = (const float*)d_in[19];
    const float* clb1    = (const float*)d_in[20];
    const float* clW2    = (const float*)d_in[21];
    const float* clb2    = (const float*)d_in[22];
    const float* prW1    = (const float*)d_in[23];
    const float* prb1    = (const float*)d_in[24];
    const float* prW2    = (const float*)d_in[25];
    const float* prb2    = (const float*)d_in[26];
    float* out = (float*)d_out;

    float *p_h, *p_h2;
    __half *p_hh, *p_hh2, *p_W1th, *p_W2th, *p_pgW1th, *p_Wpackh, *p_Abufh;
    cudaGetSymbolAddress((void**)&p_h, g_h);
    cudaGetSymbolAddress((void**)&p_h2, g_h2);
    cudaGetSymbolAddress((void**)&p_hh, g_hh);
    cudaGetSymbolAddress((void**)&p_hh2, g_hh2);
    cudaGetSymbolAddress((void**)&p_W1th, g_W1th);
    cudaGetSymbolAddress((void**)&p_W2th, g_W2th);
    cudaGetSymbolAddress((void**)&p_pgW1th, g_pgW1th);
    cudaGetSymbolAddress((void**)&p_Wpackh, g_Wpackh);
    cudaGetSymbolAddress((void**)&p_Abufh, g_Abufh);

    cudaFuncSetAttribute(encoder_fused_kernel, cudaFuncAttributeMaxDynamicSharedMemorySize, HG_DSM);
    cudaFuncSetAttribute(hgemm_kernel, cudaFuncAttributeMaxDynamicSharedMemorySize, HG_DSM);
    cudaFuncSetAttribute(pgate_kernel, cudaFuncAttributeMaxDynamicSharedMemorySize, PG_DSM);

    const int EB = (EE + 255) / 256;
    const int NB = (NN + 255) / 256;
    const int WB = (NN + 7) / 8;
    const int MB = (NN + 127) / 128;
    const int SB = (NN + 1023) / 1024;
    const int PB = (int)((PREP_S4 + 255) / 256);

    // setup
    zero_kernel<<<NB, 256>>>();
    edge1_kernel<<<EB, 256>>>(ei);
    scan1_kernel<<<SB, 1024>>>();
    scan3b_kernel<<<NB, 256>>>(SB);
    edge2_kernel<<<EB, 256>>>(ei);
    ef_kernel<<<WB, 256>>>(pos);
    prep_kernel<<<PB, 256>>>(ne_W1, ne_W2, pgW1, convW, convB);

    // fused node encoder -> h fp32 + hh half
    encoder_fused_kernel<<<MB, 1024, HG_DSM>>>(x, p_W1th, ne_b1, p_W2th, ne_b2,
                                               ne_g, ne_beta, p_h, p_hh);

    // conv layers: gather (half) + hgemm (fused postconv), ping-pong
    float* hinF = p_h;   __half* hinH = p_hh;
    float* houF = p_h2;  __half* houH = p_hh2;
    for (int l = 0; l < LL; l++) {
        gatherh_kernel<<<WB, 256>>>(hinH);
        hgemm_kernel<<<MB, 1024, HG_DSM>>>(p_Abufh, KPAD, NN, KPAD,
                                           p_Wpackh + (long)l * HH * KPAD, KPAD,
                                           convG + l * HH, convBeta + l * HH,
                                           lnG + l * HH, lnB + l * HH,
                                           hinF, houF, houH);
        float* tf = hinF; hinF = houF; houF = tf;
        __half* th = hinH; hinH = houH; houH = th;
    }
    // final h is in g_h / g_hh

    // attention pooling
    pgate_kernel<<<MB, 256, PG_DSM>>>(p_hh, p_pgW1th, pgb1, pgW2, pgb2);
    expwsum_kernel<<<NB, 256>>>();

    // heads
    heads_kernel<<<1, 256>>>(clW1, clb1, clW2, clb2, prW1, prb1, prW2, prb2, out);
}

// round 16
// speedup vs baseline: 1.0562x; 1.0562x over previous
#include <cuda_runtime.h>
#include <cuda_fp16.h>
#include <math.h>
#include <stdint.h>

#define NN 50000
#define EE 1000000
#define NIN 1281
#define K1PAD 1312
#define HH 256
#define LL 4
#define KPAD 288            // 256 Hsum + 3 sh + 16 radial + 1 deg + 12 zero pad

// ---------------- scratch ----------------
__device__ float g_h[NN * HH];
__device__ float g_h2[NN * HH];
__device__ __align__(256) __half g_hh[NN * HH];
__device__ __align__(256) __half g_hh2[NN * HH];
__device__ __align__(256) __half g_Abufh[NN * KPAD];
__device__ float g_gate[NN];
__device__ int   g_deg[NN];
__device__ int   g_rowptr[NN + 1];
__device__ int   g_cursor[NN];
__device__ int   g_csrc[EE];
__device__ __align__(256) __half g_W1th[HH * K1PAD];
__device__ __align__(256) __half g_W2th[HH * HH];
__device__ __align__(256) __half g_pgW1th[64 * HH];
__device__ __align__(256) __half g_Wpackh[LL * HH * KPAD];
__device__ float g_scal[4];
__device__ float g_Gvec[HH];
__device__ int   g_bsum[64];
__device__ unsigned g_amax;

// ---------------- helpers ----------------
__device__ __forceinline__ float warp_sum(float v) {
    #pragma unroll
    for (int o = 16; o; o >>= 1) v += __shfl_xor_sync(0xffffffffu, v, o);
    return v;
}
__device__ __forceinline__ float silu_f(float x) { return x / (1.f + expf(-x)); }
__device__ __forceinline__ uint32_t smem_u32(const void* p) {
    uint32_t a;
    asm("{ .reg .u64 t; cvta.to.shared.u64 t, %1; cvt.u32.u64 %0, t; }" : "=r"(a) : "l"(p));
    return a;
}
__device__ __forceinline__ unsigned fkey(float f) {
    unsigned u = __float_as_uint(f);
    return (u & 0x80000000u) ? ~u : (u | 0x80000000u);
}
__device__ __forceinline__ float funkey(unsigned k) {
    unsigned u = (k & 0x80000000u) ? (k & 0x7fffffffu) : ~k;
    return __uint_as_float(u);
}
#define CP_ASYNC16(dst, src) \
    asm volatile("cp.async.ca.shared.global [%0], [%1], 16;" :: "r"(dst), "l"(src))
#define CP_COMMIT() asm volatile("cp.async.commit_group;" ::: "memory")
#define CP_WAIT1()  asm volatile("cp.async.wait_group 1;" ::: "memory")
#define CP_WAIT0()  asm volatile("cp.async.wait_group 0;" ::: "memory")

__device__ __forceinline__ void ldsm_x4(unsigned& r0, unsigned& r1, unsigned& r2, unsigned& r3,
                                        uint32_t addr) {
    asm volatile("ldmatrix.sync.aligned.m8n8.x4.shared.b16 {%0,%1,%2,%3}, [%4];"
        : "=r"(r0), "=r"(r1), "=r"(r2), "=r"(r3) : "r"(addr));
}

__device__ __forceinline__ void addh8(float* a, uint4 v) {
    __half2 h0 = *reinterpret_cast<__half2*>(&v.x);
    __half2 h1 = *reinterpret_cast<__half2*>(&v.y);
    __half2 h2 = *reinterpret_cast<__half2*>(&v.z);
    __half2 h3 = *reinterpret_cast<__half2*>(&v.w);
    float2 f0 = __half22float2(h0);
    float2 f1 = __half22float2(h1);
    float2 f2 = __half22float2(h2);
    float2 f3 = __half22float2(h3);
    a[0] += f0.x; a[1] += f0.y; a[2] += f1.x; a[3] += f1.y;
    a[4] += f2.x; a[5] += f2.y; a[6] += f3.x; a[7] += f3.y;
}

__device__ __forceinline__ uint4 pack8h(const float* v) {
    uint4 r;
    __half2 h0 = __floats2half2_rn(v[0], v[1]);
    __half2 h1 = __floats2half2_rn(v[2], v[3]);
    __half2 h2 = __floats2half2_rn(v[4], v[5]);
    __half2 h3 = __floats2half2_rn(v[6], v[7]);
    r.x = *reinterpret_cast<unsigned*>(&h0);
    r.y = *reinterpret_cast<unsigned*>(&h1);
    r.z = *reinterpret_cast<unsigned*>(&h2);
    r.w = *reinterpret_cast<unsigned*>(&h3);
    return r;
}

// ---------------- setup ----------------
__global__ void zero_kernel() {
    int i = blockIdx.x * 256 + threadIdx.x;
    if (i < NN) { g_deg[i] = 0; g_cursor[i] = 0; }
    if (i < HH) g_Gvec[i] = 0.f;
    if (i < 4) g_scal[i] = 0.f;
    if (i == 0) { g_rowptr[0] = 0; g_amax = 0u; }
}

__global__ void edge1_kernel(const int* __restrict__ ei) {
    int e = blockIdx.x * 256 + threadIdx.x;
    if (e >= EE) return;
    atomicAdd(&g_deg[ei[EE + e]], 1);
}

__global__ void scan1_kernel() {
    __shared__ int s[1024];
    int tid = threadIdx.x;
    int gid = blockIdx.x * 1024 + tid;
    int v = (gid < NN) ? g_deg[gid] : 0;
    s[tid] = v;
    __syncthreads();
    for (int off = 1; off < 1024; off <<= 1) {
        int t = (tid >= off) ? s[tid - off] : 0;
        __syncthreads();
        s[tid] += t;
        __syncthreads();
    }
    if (gid < NN) g_rowptr[gid + 1] = s[tid];
    if (tid == 1023) g_bsum[blockIdx.x] = s[1023];
}

__global__ void scan3b_kernel(int nb) {
    __shared__ int pref[64];
    int tid = threadIdx.x;
    if (tid < 64) pref[tid] = (tid < nb) ? g_bsum[tid] : 0;
    __syncthreads();
    for (int off = 1; off < 64; off <<= 1) {
        int t = (tid >= off && tid < 64) ? pref[tid - off] : 0;
        __syncthreads();
        if (tid < 64) pref[tid] += t;
        __syncthreads();
    }
    int gid = blockIdx.x * 256 + tid;
    if (gid < NN) {
        int b = gid >> 10;
        if (b > 0) g_rowptr[gid + 1] += pref[b - 1];
    }
}

__global__ void edge2_kernel(const int* __restrict__ ei) {
    int e = blockIdx.x * 256 + threadIdx.x;
    if (e >= EE) return;
    int s = ei[e];
    int d = ei[EE + e];
    int slot = atomicAdd(&g_cursor[d], 1);
    g_csrc[g_rowptr[d] + slot] = s;
}

// warp-per-node edge-feature aggregation
__global__ void ef_kernel(const float* __restrict__ pos) {
    int w = (blockIdx.x * 256 + threadIdx.x) >> 5;
    int lane = threadIdx.x & 31;
    if (w >= NN) return;
    const float wd = 0.1953125f;
    const float cstep = 10.f / 15.f;
    float Ej[16];
    #pragma unroll
    for (int j = 0; j < 16; j++) {
        float c = cstep * (float)j;
        Ej[j] = expf(-wd * c * c);
    }
    float px = pos[3 * w + 0], py = pos[3 * w + 1], pz = pos[3 * w + 2];
    float shx = 0.f, shy = 0.f, shz = 0.f;
    float rad[16];
    #pragma unroll
    for (int j = 0; j < 16; j++) rad[j] = 0.f;
    int beg = g_rowptr[w], end = g_rowptr[w + 1];
    for (int e = beg + lane; e < end; e += 32) {
        int s = g_csrc[e];
        float rx = px - pos[3 * s + 0];
        float ry = py - pos[3 * s + 1];
        float rz = pz - pos[3 * s + 2];
        float dist = sqrtf(rx * rx + ry * ry + rz * rz);
        float inv = 1.f / fmaxf(dist, 1e-12f);
        shx += rx * inv; shy += ry * inv; shz += rz * inv;
        if (dist < 18.f) {
            float A = expf(-wd * dist * dist);
            float r1 = expf(2.f * wd * cstep * dist);
            float r2 = r1 * r1, r4 = r2 * r2, r8 = r4 * r4;
            float p[16];
            p[0] = A;         p[1] = A * r1;
            p[2] = p[0] * r2; p[3] = p[1] * r2;
            #pragma unroll
            for (int j = 0; j < 4; j++) p[4 + j] = p[j] * r4;
            #pragma unroll
            for (int j = 0; j < 8; j++) p[8 + j] = p[j] * r8;
            #pragma unroll
            for (int j = 0; j < 16; j++) rad[j] += p[j] * Ej[j];
        } else {
            #pragma unroll
            for (int j = 0; j < 16; j++) {
                float t = dist - cstep * (float)j;
                rad[j] += expf(-wd * t * t);
            }
        }
    }
    shx = warp_sum(shx);
    shy = warp_sum(shy);
    shz = warp_sum(shz);
    #pragma unroll
    for (int j = 0; j < 16; j++) rad[j] = warp_sum(rad[j]);
    if (lane == 0) {
        __half* ab = g_Abufh + (long)w * KPAD + 256;
        ab[0] = __float2half_rn(shx);
        ab[1] = __float2half_rn(shy);
        ab[2] = __float2half_rn(shz);
        #pragma unroll
        for (int j = 0; j < 16; j++) ab[3 + j] = __float2half_rn(rad[j]);
        ab[19] = __float2half_rn((float)(end - beg));
        #pragma unroll
        for (int j = 20; j < 32; j++) ab[j] = __float2half_rn(0.f);
    }
}

// merged weight preparation
#define PREP_S1 ((long)HH * K1PAD)
#define PREP_S2 (PREP_S1 + (long)HH * HH)
#define PREP_S3 (PREP_S2 + 64L * HH)
#define PREP_S4 (PREP_S3 + (long)LL * HH * KPAD)
__global__ void prep_kernel(const float* __restrict__ ne_W1, const float* __restrict__ ne_W2,
                            const float* __restrict__ pgW1,
                            const float* __restrict__ convW, const float* __restrict__ convB) {
    long idx = (long)blockIdx.x * 256 + threadIdx.x;
    if (idx < PREP_S1) {
        int n = (int)(idx / K1PAD), k = (int)(idx % K1PAD);
        g_W1th[idx] = __float2half_rn((k < NIN) ? ne_W1[(long)k * HH + n] : 0.f);
    } else if (idx < PREP_S2) {
        long r = idx - PREP_S1;
        int n = (int)(r / HH), k = (int)(r % HH);
        g_W2th[r] = __float2half_rn(ne_W2[(long)k * HH + n]);
    } else if (idx < PREP_S3) {
        long r = idx - PREP_S2;
        int n = (int)(r / HH), k = (int)(r % HH);
        g_pgW1th[r] = __float2half_rn(pgW1[(long)k * 64 + n]);
    } else if (idx < PREP_S4) {
        long r = idx - PREP_S3;
        int l = (int)(r / (HH * KPAD));
        int rem = (int)(r % (HH * KPAD));
        int n = rem / KPAD, k = rem % KPAD;
        float v = 0.f;
        if (k < 275)       v = convW[((long)l * 275 + k) * HH + n];
        else if (k == 275) v = convB[l * HH + n];
        g_Wpackh[r] = __float2half_rn(v);
    }
}

// ---------------- shared GEMM constants ----------------
#define ASTH 40
#define STGH ((128 + 256) * ASTH)
#define EPI_ST 258
#define HG_DSM (128 * EPI_ST * 4)

// ================= fused node encoder: 512 threads, warp tile 64x32, LDSM ========
#define AT2_ST 264
#define B2_STG (256 * ASTH)
__global__ __launch_bounds__(512, 1)
void encoder_fused_kernel(const float* __restrict__ x,
                          const __half* __restrict__ W1t,
                          const float* __restrict__ b1,
                          const __half* __restrict__ W2t,
                          const float* __restrict__ b2,
                          const float* __restrict__ lnG, const float* __restrict__ lnB,
                          float* __restrict__ houtF, __half* __restrict__ houtH) {
    extern __shared__ float smf[];
    __half* sm = (__half*)smf;
    int t = threadIdx.x;
    int lane = t & 31, warp = t >> 5;
    int wr = warp >> 3;
    int wc = warp & 7;
    int rowBase = blockIdx.x * 128;
    uint32_t smb = smem_u32(sm);

    int aRow = t >> 2, aCq = t & 3;
    int aGr = rowBase + aRow;
    if (aGr >= NN) aGr = NN - 1;

    int kq = lane & 3;
    int kg = lane >> 2;

    // ldmatrix row terms (in halves)
    uint32_t aTermS = (uint32_t)((wr * 64 + (lane & 15)) * ASTH + ((lane >> 4) << 3));
    uint32_t aTerm2 = (uint32_t)((wr * 64 + (lane & 15)) * AT2_ST + ((lane >> 4) << 3));
    uint32_t bTermS = (uint32_t)((wc * 32 + ((lane >> 4) << 3) + (lane & 7)) * ASTH
                                 + (((lane >> 3) & 1) << 3));

    float acc[4][4][4];
    #pragma unroll
    for (int mi = 0; mi < 4; mi++)
        #pragma unroll
        for (int ni = 0; ni < 4; ni++)
            #pragma unroll
            for (int q = 0; q < 4; q++) acc[mi][ni][q] = 0.f;

    // ---------- phase 1: K = NIN ----------
    {
        const int K = NIN;
        int nT = (K + 31) >> 5;
        auto load_B = [&](int i, int s) {
            int k0 = i << 5;
            uint32_t sbase = smb + (uint32_t)(s * STGH) * 2u;
            #pragma unroll
            for (int it = 0; it < 2; it++) {
                int c = it * 512 + t;
                int n = c >> 2, cq = c & 3;
                const __half* src = W1t + (long)n * K1PAD + k0 + cq * 8;
                uint32_t dst = sbase + (uint32_t)(128 * ASTH + n * ASTH + cq * 8) * 2u;
                CP_ASYNC16(dst, src);
            }
        };
        auto ldg_A = [&](int i, float* r) {
            int k0 = (i << 5) + aCq * 8;
            const float* src = x + (long)aGr * NIN + k0;
            #pragma unroll
            for (int j = 0; j < 8; j++)
                r[j] = (k0 + j < K) ? src[j] : 0.f;
        };
        auto sts_A = [&](int s, const float* r) {
            __half* dst = sm + s * STGH + aRow * ASTH + aCq * 8;
            *(uint4*)dst = pack8h(r);
        };

        {
            float r0[8];
            ldg_A(0, r0); sts_A(0, r0);
            ldg_A(1, r0); sts_A(1, r0);
        }
        load_B(0, 0);
        CP_COMMIT();
        load_B(1, 1);
        CP_COMMIT();

        for (int i = 0; i < nT; i++) {
            CP_WAIT1();
            __syncthreads();
            float aStage[8];
            bool doStage = (i + 2 < nT);
            if (doStage) {
                ldg_A(i + 2, aStage);
                load_B(i + 2, (i + 2) % 3);
            }
            CP_COMMIT();

            uint32_t asB = smb + (uint32_t)((i % 3) * STGH) * 2u;
            uint32_t bsB = asB + (uint32_t)(128 * ASTH) * 2u;
            #pragma unroll
            for (int ks = 0; ks < 2; ks++) {
                unsigned af[4][4], bf[4][2];
                #pragma unroll
                for (int mi = 0; mi < 4; mi++)
                    ldsm_x4(af[mi][0], af[mi][1], af[mi][2], af[mi][3],
                            asB + (aTermS + (uint32_t)(mi * 16 * ASTH + ks * 16)) * 2u);
                #pragma unroll
                for (int nj = 0; nj < 2; nj++)
                    ldsm_x4(bf[nj * 2][0], bf[nj * 2][1], bf[nj * 2 + 1][0], bf[nj * 2 + 1][1],
                            bsB + (bTermS + (uint32_t)(nj * 16 * ASTH + ks * 16)) * 2u);
                #pragma unroll
                for (int mi = 0; mi < 4; mi++)
                    #pragma unroll
                    for (int ni = 0; ni < 4; ni++) {
                        asm volatile(
                            "mma.sync.aligned.m16n8k16.row.col.f32.f16.f16.f32 "
                            "{%0,%1,%2,%3}, {%4,%5,%6,%7}, {%8,%9}, {%0,%1,%2,%3};"
                            : "+f"(acc[mi][ni][0]), "+f"(acc[mi][ni][1]),
                              "+f"(acc[mi][ni][2]), "+f"(acc[mi][ni][3])
                            : "r"(af[mi][0]), "r"(af[mi][1]), "r"(af[mi][2]), "r"(af[mi][3]),
                              "r"(bf[ni][0]), "r"(bf[ni][1]));
                    }
            }
            if (doStage) sts_A((i + 2) % 3, aStage);
        }
    }

    // ---------- phase boundary: t1 tile = silu(acc + b1) -> smem half [128][AT2_ST] ----
    CP_WAIT0();
    __syncthreads();
    #pragma unroll
    for (int mi = 0; mi < 4; mi++) {
        #pragma unroll
        for (int ni = 0; ni < 4; ni++) {
            int rloc0 = wr * 64 + mi * 16 + kg;
            int c0 = wc * 32 + ni * 8 + kq * 2;
            #pragma unroll
            for (int half = 0; half < 2; half++) {
                int rl = rloc0 + half * 8;
                float v0 = silu_f(acc[mi][ni][half * 2 + 0] + b1[c0]);
                float v1 = silu_f(acc[mi][ni][half * 2 + 1] + b1[c0 + 1]);
                *(__half2*)(sm + rl * AT2_ST + c0) = __floats2half2_rn(v0, v1);
            }
        }
    }
    __syncthreads();

    #pragma unroll
    for (int mi = 0; mi < 4; mi++)
        #pragma unroll
        for (int ni = 0; ni < 4; ni++)
            #pragma unroll
            for (int q = 0; q < 4; q++) acc[mi][ni][q] = 0.f;

    // ---------- phase 2: K = 256, A persistent, B = W2t streamed ----------
    {
        __half* B2 = sm + 128 * AT2_ST;
        uint32_t b2b = smem_u32(B2);
        auto load_B2 = [&](int i, int s) {
            int k0 = i << 5;
            uint32_t sbase = b2b + (uint32_t)(s * B2_STG) * 2u;
            #pragma unroll
            for (int it = 0; it < 2; it++) {
                int c = it * 512 + t;
                int n = c >> 2, cq = c & 3;
                const __half* src = W2t + (long)n * HH + k0 + cq * 8;
                uint32_t dst = sbase + (uint32_t)(n * ASTH + cq * 8) * 2u;
                CP_ASYNC16(dst, src);
            }
        };
        load_B2(0, 0);
        CP_COMMIT();
        load_B2(1, 1);
        CP_COMMIT();
        for (int i = 0; i < 8; i++) {
            CP_WAIT1();
            __syncthreads();
            if (i + 2 < 8) load_B2(i + 2, (i + 2) % 3);
            CP_COMMIT();
            int k0 = i << 5;
            uint32_t bsB = b2b + (uint32_t)((i % 3) * B2_STG) * 2u;
            #pragma unroll
            for (int ks = 0; ks < 2; ks++) {
                unsigned af[4][4], bf[4][2];
                #pragma unroll
                for (int mi = 0; mi < 4; mi++)
                    ldsm_x4(af[mi][0], af[mi][1], af[mi][2], af[mi][3],
                            smb + (aTerm2 + (uint32_t)(mi * 16 * AT2_ST + k0 + ks * 16)) * 2u);
                #pragma unroll
                for (int nj = 0; nj < 2; nj++)
                    ldsm_x4(bf[nj * 2][0], bf[nj * 2][1], bf[nj * 2 + 1][0], bf[nj * 2 + 1][1],
                            bsB + (bTermS + (uint32_t)(nj * 16 * ASTH + ks * 16)) * 2u);
                #pragma unroll
                for (int mi = 0; mi < 4; mi++)
                    #pragma unroll
                    for (int ni = 0; ni < 4; ni++) {
                        asm volatile(
                            "mma.sync.aligned.m16n8k16.row.col.f32.f16.f16.f32 "
                            "{%0,%1,%2,%3}, {%4,%5,%6,%7}, {%8,%9}, {%0,%1,%2,%3};"
                            : "+f"(acc[mi][ni][0]), "+f"(acc[mi][ni][1]),
                              "+f"(acc[mi][ni][2]), "+f"(acc[mi][ni][3])
                            : "r"(af[mi][0]), "r"(af[mi][1]), "r"(af[mi][2]), "r"(af[mi][3]),
                              "r"(bf[ni][0]), "r"(bf[ni][1]));
                    }
            }
        }
    }

    // ---------- LN epilogue ----------
    CP_WAIT0();
    __syncthreads();
    #pragma unroll
    for (int mi = 0; mi < 4; mi++) {
        #pragma unroll
        for (int ni = 0; ni < 4; ni++) {
            int rloc0 = wr * 64 + mi * 16 + kg;
            int c0 = wc * 32 + ni * 8 + kq * 2;
            #pragma unroll
            for (int half = 0; half < 2; half++) {
                int rl = rloc0 + half * 8;
                #pragma unroll
                for (int q = 0; q < 2; q++) {
                    int c = c0 + q;
                    smf[rl * EPI_ST + c] = acc[mi][ni][half * 2 + q] + b2[c];
                }
            }
        }
    }
    __syncthreads();
    #pragma unroll
    for (int rr = 0; rr < 8; rr++) {
        int rl = rr * 16 + warp;
        int gr = rowBase + rl;
        if (gr >= NN) continue;
        float xv[8];
        #pragma unroll
        for (int i = 0; i < 8; i++) xv[i] = smf[rl * EPI_ST + lane + 32 * i];
        float s = 0.f;
        #pragma unroll
        for (int i = 0; i < 8; i++) s += xv[i];
        s = warp_sum(s);
        float m = s * (1.f / 256.f);
        float qv = 0.f;
        #pragma unroll
        for (int i = 0; i < 8; i++) { float d = xv[i] - m; qv += d * d; }
        qv = warp_sum(qv);
        float rs = rsqrtf(qv * (1.f / 256.f) + 1e-5f);
        float* of = houtF + (long)gr * HH;
        __half* oh = houtH + (long)gr * HH;
        #pragma unroll
        for (int i = 0; i < 8; i++) {
            int c = lane + 32 * i;
            float y = (xv[i] - m) * rs * lnG[c] + lnB[c];
            of[c] = y;
            oh[c] = __float2half_rn(y);
        }
    }
}

// ================= FP16 GEMM (conv layers): 512 threads, LDSM fragments ======
__global__ __launch_bounds__(512, 1)
void hgemm_kernel(const __half* __restrict__ A, int lda, int M, int K,
                  const __half* __restrict__ Bt, int ldb,
                  const float* __restrict__ p1, const float* __restrict__ p2,
                  const float* __restrict__ p3, const float* __restrict__ p4,
                  const float* __restrict__ hinF,
                  float* __restrict__ houtF, __half* __restrict__ houtH) {
    extern __shared__ float smf[];
    __half* sm = (__half*)smf;
    int t = threadIdx.x;
    int lane = t & 31, warp = t >> 5;
    int wr = warp >> 3;
    int wc = warp & 7;
    int rowBase = blockIdx.x * 128;
    uint32_t smb = smem_u32(sm);

    int nT = (K + 31) >> 5;
    int aRow = t >> 2, aCq = t & 3;
    int aGr = rowBase + aRow;
    if (aGr >= M) aGr = M - 1;

    uint32_t aTermS = (uint32_t)((wr * 64 + (lane & 15)) * ASTH + ((lane >> 4) << 3));
    uint32_t bTermS = (uint32_t)((wc * 32 + ((lane >> 4) << 3) + (lane & 7)) * ASTH
                                 + (((lane >> 3) & 1) << 3));

    float acc[4][4][4];
    #pragma unroll
    for (int mi = 0; mi < 4; mi++)
        #pragma unroll
        for (int ni = 0; ni < 4; ni++)
            #pragma unroll
            for (int q = 0; q < 4; q++) acc[mi][ni][q] = 0.f;

    auto load_stage = [&](int i, int s) {
        int k0 = i << 5;
        uint32_t sbase = smb + (uint32_t)(s * STGH) * 2u;
        {
            const __half* src = A + (long)aGr * lda + k0 + aCq * 8;
            uint32_t dst = sbase + (uint32_t)(aRow * ASTH + aCq * 8) * 2u;
            CP_ASYNC16(dst, src);
        }
        #pragma unroll
        for (int it = 0; it < 2; it++) {
            int c = it * 512 + t;
            int n = c >> 2, cq = c & 3;
            const __half* src = Bt + (long)n * ldb + k0 + cq * 8;
            uint32_t dst = sbase + (uint32_t)(128 * ASTH + n * ASTH + cq * 8) * 2u;
            CP_ASYNC16(dst, src);
        }
    };

    load_stage(0, 0);
    CP_COMMIT();
    if (nT > 1) load_stage(1, 1);
    CP_COMMIT();

    int kq = lane & 3;
    int kg = lane >> 2;

    for (int i = 0; i < nT; i++) {
        CP_WAIT1();
        __syncthreads();
        if (i + 2 < nT) load_stage(i + 2, (i + 2) % 3);
        CP_COMMIT();

        uint32_t asB = smb + (uint32_t)((i % 3) * STGH) * 2u;
        uint32_t bsB = asB + (uint32_t)(128 * ASTH) * 2u;
        #pragma unroll
        for (int ks = 0; ks < 2; ks++) {
            unsigned af[4][4], bf[4][2];
            #pragma unroll
            for (int mi = 0; mi < 4; mi++)
                ldsm_x4(af[mi][0], af[mi][1], af[mi][2], af[mi][3],
                        asB + (aTermS + (uint32_t)(mi * 16 * ASTH + ks * 16)) * 2u);
            #pragma unroll
            for (int nj = 0; nj < 2; nj++)
                ldsm_x4(bf[nj * 2][0], bf[nj * 2][1], bf[nj * 2 + 1][0], bf[nj * 2 + 1][1],
                        bsB + (bTermS + (uint32_t)(nj * 16 * ASTH + ks * 16)) * 2u);
            #pragma unroll
            for (int mi = 0; mi < 4; mi++)
                #pragma unroll
                for (int ni = 0; ni < 4; ni++) {
                    asm volatile(
                        "mma.sync.aligned.m16n8k16.row.col.f32.f16.f16.f32 "
                        "{%0,%1,%2,%3}, {%4,%5,%6,%7}, {%8,%9}, {%0,%1,%2,%3};"
                        : "+f"(acc[mi][ni][0]), "+f"(acc[mi][ni][1]),
                          "+f"(acc[mi][ni][2]), "+f"(acc[mi][ni][3])
                        : "r"(af[mi][0]), "r"(af[mi][1]), "r"(af[mi][2]), "r"(af[mi][3]),
                          "r"(bf[ni][0]), "r"(bf[ni][1]));
                }
        }
    }

    // postconv epilogue (mode 2)
    __syncthreads();
    #pragma unroll
    for (int mi = 0; mi < 4; mi++) {
        #pragma unroll
        for (int ni = 0; ni < 4; ni++) {
            int rloc0 = wr * 64 + mi * 16 + kg;
            int c0 = wc * 32 + ni * 8 + kq * 2;
            #pragma unroll
            for (int half = 0; half < 2; half++) {
                int rl = rloc0 + half * 8;
                #pragma unroll
                for (int q = 0; q < 2; q++) {
                    int c = c0 + q;
                    smf[rl * EPI_ST + c] = acc[mi][ni][half * 2 + q];
                }
            }
        }
    }
    __syncthreads();

    #pragma unroll
    for (int rr = 0; rr < 8; rr++) {
        int rl = rr * 16 + warp;
        int gr = rowBase + rl;
        if (gr >= M) continue;
        const float* hp = hinF + (long)gr * HH;
        float* of = houtF + (long)gr * HH;
        __half* oh = houtH + (long)gr * HH;
        float x[8];
        float s = 0.f;
        #pragma unroll
        for (int i = 0; i < 8; i++) {
            x[i] = silu_f(smf[rl * EPI_ST + lane + 32 * i]);
            s += x[i];
        }
        s = warp_sum(s);
        float m1 = s * (1.f / 256.f);
        float qv = 0.f;
        #pragma unroll
        for (int i = 0; i < 8; i++) { float d = x[i] - m1; qv += d * d; }
        qv = warp_sum(qv);
        float rs1 = rsqrtf(qv * (1.f / 256.f) + 1e-5f);
        float z[8];
        float s2 = 0.f;
        #pragma unroll
        for (int i = 0; i < 8; i++) {
            int c = lane + 32 * i;
            float y = (x[i] - m1) * rs1 * p1[c] + p2[c];
            float zz = hp[c] + y;
            z[i] = zz; s2 += zz;
        }
        s2 = warp_sum(s2);
        float m2 = s2 * (1.f / 256.f);
        float q2 = 0.f;
        #pragma unroll
        for (int i = 0; i < 8; i++) { float d = z[i] - m2; q2 += d * d; }
        q2 = warp_sum(q2);
        float rs2 = rsqrtf(q2 * (1.f / 256.f) + 1e-5f);
        #pragma unroll
        for (int i = 0; i < 8; i++) {
            int c = lane + 32 * i;
            float y = (z[i] - m2) * rs2 * p3[c] + p4[c];
            of[c] = y;
            oh[c] = __float2half_rn(y);
        }
    }
}

// ---------------- gather (half source) ----------------
__global__ void gatherh_kernel(const __half* __restrict__ hinh) {
    int w = (blockIdx.x * 256 + threadIdx.x) >> 5;
    int lane = threadIdx.x & 31;
    if (w >= NN) return;
    float a[8], b[8];
    #pragma unroll
    for (int j = 0; j < 8; j++) { a[j] = 0.f; b[j] = 0.f; }
    const uint4* base = (const uint4*)hinh;
    int beg = g_rowptr[w], end = g_rowptr[w + 1];
    int e = beg;
    for (; e + 1 < end; e += 2) {
        int s0 = g_csrc[e], s1 = g_csrc[e + 1];
        uint4 v = base[(long)s0 * 32 + lane];
        uint4 u = base[(long)s1 * 32 + lane];
        addh8(a, v);
        addh8(b, u);
    }
    if (e < end) {
        uint4 v = base[(long)g_csrc[e] * 32 + lane];
        addh8(a, v);
    }
    float out[8];
    #pragma unroll
    for (int j = 0; j < 8; j++) out[j] = a[j] + b[j];
    *(uint4*)(g_Abufh + (long)w * KPAD + lane * 8) = pack8h(out);
}

// ================= pool gate GEMM (fp16) + fused gate dot + block max =================
#define PG_STG ((128 + 64) * ASTH)
#define PG_DSM (3 * PG_STG * 2)
__global__ __launch_bounds__(256, 2)
void pgate_kernel(const __half* __restrict__ hh, const __half* __restrict__ Bt,
                  const float* __restrict__ bias,
                  const float* __restrict__ pgW2, const float* __restrict__ pgb2) {
    extern __shared__ __half smh[];
    __shared__ float wmax[8];
    float* smf = (float*)smh;
    int t = threadIdx.x;
    int lane = t & 31, warp = t >> 5;
    int wr = warp >> 2;
    int wc = warp & 3;
    int rowBase = blockIdx.x * 128;
    uint32_t smb = smem_u32(smh);

    float acc[4][2][4];
    #pragma unroll
    for (int mi = 0; mi < 4; mi++)
        #pragma unroll
        for (int ni = 0; ni < 2; ni++)
            #pragma unroll
            for (int q = 0; q < 4; q++) acc[mi][ni][q] = 0.f;

    auto load_stage = [&](int i, int s) {
        int k0 = i << 5;
        uint32_t sbase = smb + (uint32_t)(s * PG_STG) * 2u;
        #pragma unroll
        for (int it = 0; it < 2; it++) {
            int c = it * 256 + t;
            int row = c >> 2, cq = c & 3;
            int gr = rowBase + row;
            if (gr >= NN) gr = NN - 1;
            const __half* src = hh + (long)gr * HH + k0 + cq * 8;
            uint32_t dst = sbase + (uint32_t)(row * ASTH + cq * 8) * 2u;
            CP_ASYNC16(dst, src);
        }
        {
            int n = t >> 2, cq = t & 3;
            const __half* src = Bt + (long)n * HH + k0 + cq * 8;
            uint32_t dst = sbase + (uint32_t)(128 * ASTH + n * ASTH + cq * 8) * 2u;
            CP_ASYNC16(dst, src);
        }
    };

    load_stage(0, 0);
    CP_COMMIT();
    load_stage(1, 1);
    CP_COMMIT();

    int kq = lane & 3;
    int kg = lane >> 2;

    for (int i = 0; i < 8; i++) {
        CP_WAIT1();
        __syncthreads();
        if (i + 2 < 8) load_stage(i + 2, (i + 2) % 3);
        CP_COMMIT();

        const __half* As = smh + (i % 3) * PG_STG;
        const __half* Bs = As + 128 * ASTH;
        #pragma unroll
        for (int ks = 0; ks < 2; ks++) {
            int ko = ks * 16;
            unsigned af[4][4], bf[2][2];
            #pragma unroll
            for (int mi = 0; mi < 4; mi++) {
                int ar = wr * 64 + mi * 16 + kg;
                af[mi][0] = *(const unsigned*)(As + ar * ASTH + ko + kq * 2);
                af[mi][1] = *(const unsigned*)(As + (ar + 8) * ASTH + ko + kq * 2);
                af[mi][2] = *(const unsigned*)(As + ar * ASTH + ko + kq * 2 + 8);
                af[mi][3] = *(const unsigned*)(As + (ar + 8) * ASTH + ko + kq * 2 + 8);
            }
            #pragma unroll
            for (int ni = 0; ni < 2; ni++) {
                int bn = wc * 16 + ni * 8 + kg;
                bf[ni][0] = *(const unsigned*)(Bs + bn * ASTH + ko + kq * 2);
                bf[ni][1] = *(const unsigned*)(Bs + bn * ASTH + ko + kq * 2 + 8);
            }
            #pragma unroll
            for (int mi = 0; mi < 4; mi++)
                #pragma unroll
                for (int ni = 0; ni < 2; ni++) {
                    asm volatile(
                        "mma.sync.aligned.m16n8k16.row.col.f32.f16.f16.f32 "
                        "{%0,%1,%2,%3}, {%4,%5,%6,%7}, {%8,%9}, {%0,%1,%2,%3};"
                        : "+f"(acc[mi][ni][0]), "+f"(acc[mi][ni][1]),
                          "+f"(acc[mi][ni][2]), "+f"(acc[mi][ni][3])
                        : "r"(af[mi][0]), "r"(af[mi][1]), "r"(af[mi][2]), "r"(af[mi][3]),
                          "r"(bf[ni][0]), "r"(bf[ni][1]));
                }
        }
    }

    CP_WAIT0();
    __syncthreads();
    #pragma unroll
    for (int mi = 0; mi < 4; mi++) {
        #pragma unroll
        for (int ni = 0; ni < 2; ni++) {
            int r0 = wr * 64 + mi * 16 + kg;
            int c0 = wc * 16 + ni * 8 + kq * 2;
            #pragma unroll
            for (int half = 0; half < 2; half++) {
                int rl = r0 + half * 8;
                #pragma unroll
                for (int q = 0; q < 2; q++) {
                    int c = c0 + q;
                    smf[rl * 64 + c] = silu_f(acc[mi][ni][half * 2 + q] + bias[c]);
                }
            }
        }
    }
    __syncthreads();
    float lmax = -1e30f;
    float w0 = pgW2[lane], w1 = pgW2[32 + lane];
    for (int rr = 0; rr < 16; rr++) {
        int rl = rr * 8 + warp;
        int gr = rowBase + rl;
        if (gr >= NN) continue;
        float v = smf[rl * 64 + lane] * w0 + smf[rl * 64 + 32 + lane] * w1;
        v = warp_sum(v);
        if (lane == 0) {
            float g = v + pgb2[0];
            g_gate[gr] = g;
            lmax = fmaxf(lmax, g);
        }
    }
    if (lane == 0) wmax[warp] = lmax;
    __syncthreads();
    if (t == 0) {
        float m = wmax[0];
        #pragma unroll
        for (int j = 1; j < 8; j++) m = fmaxf(m, wmax[j]);
        atomicMax(&g_amax, fkey(m));
    }
}

// ---------------- pooling tail ----------------
__global__ void expwsum_kernel() {
    __shared__ float e[256];
    __shared__ float red[256];
    int tid = threadIdx.x;
    int n = blockIdx.x * 256 + tid;
    float M = funkey(g_amax);
    float ev = 0.f;
    if (n < NN) ev = expf(g_gate[n] - M);
    e[tid] = ev;
    red[tid] = ev;
    __syncthreads();
    for (int o = 128; o; o >>= 1) {
        if (tid < o) red[tid] += red[tid + o];
        __syncthreads();
    }
    if (tid == 0) atomicAdd(&g_scal[1], red[0]);
    float acc = 0.f;
    int n0 = blockIdx.x * 256;
    for (int i = 0; i < 256; i++) {
        int nn = n0 + i;
        if (nn >= NN) break;
        acc += e[i] * g_h[(long)nn * HH + tid];
    }
    atomicAdd(&g_Gvec[tid], acc);
}

// ---------------- heads ----------------
__global__ void heads_kernel(const float* __restrict__ clW1, const float* __restrict__ clb1,
                             const float* __restrict__ clW2, const float* __restrict__ clb2,
                             const float* __restrict__ prW1, const float* __restrict__ prb1,
                             const float* __restrict__ prW2, const float* __restrict__ prb2,
                             float* __restrict__ out) {
    __shared__ float emb[256], c1[128], p1[256], pr[128];
    __shared__ float nrm;
    int t = threadIdx.x;
    float se = g_scal[1];
    float ev = g_Gvec[t] / se;
    emb[t] = ev;
    out[132 + t] = ev;
    __syncthreads();
    if (t < 128) {
        float a = 0.f;
        for (int k = 0; k < 256; k++) a += emb[k] * clW1[k * 128 + t];
        a += clb1[t];
        c1[t] = silu_f(a);
    }
    {
        float a = 0.f;
        for (int k = 0; k < 256; k++) a += emb[k] * prW1[k * 256 + t];
        a += prb1[t];
        p1[t] = silu_f(a);
    }
    __syncthreads();
    if (t < 4) {
        float a = 0.f;
        for (int k = 0; k < 128; k++) a += c1[k] * clW2[k * 4 + t];
        out[t] = a + clb2[t];
    }
    if (t < 128) {
        float a = 0.f;
        for (int k = 0; k < 256; k++) a += p1[k] * prW2[k * 128 + t];
        pr[t] = a + prb2[t];
    }
    __syncthreads();
    if (t == 0) {
        float s = 0.f;
        for (int k = 0; k < 128; k++) s += pr[k] * pr[k];
        nrm = fmaxf(sqrtf(s), 1e-12f);
    }
    __syncthreads();
    if (t < 128) out[4 + t] = pr[t] / nrm;
}

// ---------------- launch ----------------
extern "C" void kernel_launch(void* const* d_in, const int* in_sizes, int n_in,
                              void* d_out, int out_size) {
    const float* x       = (const float*)d_in[0];
    const float* pos     = (const float*)d_in[1];
    const int*   ei      = (const int*)d_in[2];
    const float* ne_W1   = (const float*)d_in[3];
    const float* ne_b1   = (const float*)d_in[4];
    const float* ne_W2   = (const float*)d_in[5];
    const float* ne_b2   = (const float*)d_in[6];
    const float* ne_g    = (const float*)d_in[7];
    const float* ne_beta = (const float*)d_in[8];
    const float* convW   = (const float*)d_in[9];
    const float* convB   = (const float*)d_in[10];
    const float* convG   = (const float*)d_in[11];
    const float* convBeta= (const float*)d_in[12];
    const float* lnG     = (const float*)d_in[13];
    const float* lnB     = (const float*)d_in[14];
    const float* pgW1    = (const float*)d_in[15];
    const float* pgb1    = (const float*)d_in[16];
    const float* pgW2    = (const float*)d_in[17];
    const float* pgb2    = (const float*)d_in[18];
    const float* clW1    = (const float*)d_in[19];
    const float* clb1    = (const float*)d_in[20];
    const float* clW2    = (const float*)d_in[21];
    const float* clb2    = (const float*)d_in[22];
    const float* prW1    = (const float*)d_in[23];
    const float* prb1    = (const float*)d_in[24];
    const float* prW2    = (const float*)d_in[25];
    const float* prb2    = (const float*)d_in[26];
    float* out = (float*)d_out;

    float *p_h, *p_h2;
    __half *p_hh, *p_hh2, *p_W1th, *p_W2th, *p_pgW1th, *p_Wpackh, *p_Abufh;
    cudaGetSymbolAddress((void**)&p_h, g_h);
    cudaGetSymbolAddress((void**)&p_h2, g_h2);
    cudaGetSymbolAddress((void**)&p_hh, g_hh);
    cudaGetSymbolAddress((void**)&p_hh2, g_hh2);
    cudaGetSymbolAddress((void**)&p_W1th, g_W1th);
    cudaGetSymbolAddress((void**)&p_W2th, g_W2th);
    cudaGetSymbolAddress((void**)&p_pgW1th, g_pgW1th);
    cudaGetSymbolAddress((void**)&p_Wpackh, g_Wpackh);
    cudaGetSymbolAddress((void**)&p_Abufh, g_Abufh);

    cudaFuncSetAttribute(encoder_fused_kernel, cudaFuncAttributeMaxDynamicSharedMemorySize, HG_DSM);
    cudaFuncSetAttribute(hgemm_kernel, cudaFuncAttributeMaxDynamicSharedMemorySize, HG_DSM);
    cudaFuncSetAttribute(pgate_kernel, cudaFuncAttributeMaxDynamicSharedMemorySize, PG_DSM);

    const int EB = (EE + 255) / 256;
    const int NB = (NN + 255) / 256;
    const int WB = (NN + 7) / 8;
    const int MB = (NN + 127) / 128;
    const int SB = (NN + 1023) / 1024;
    const int PB = (int)((PREP_S4 + 255) / 256);

    // setup
    zero_kernel<<<NB, 256>>>();
    edge1_kernel<<<EB, 256>>>(ei);
    scan1_kernel<<<SB, 1024>>>();
    scan3b_kernel<<<NB, 256>>>(SB);
    edge2_kernel<<<EB, 256>>>(ei);
    ef_kernel<<<WB, 256>>>(pos);
    prep_kernel<<<PB, 256>>>(ne_W1, ne_W2, pgW1, convW, convB);

    // fused node encoder -> h fp32 + hh half
    encoder_fused_kernel<<<MB, 512, HG_DSM>>>(x, p_W1th, ne_b1, p_W2th, ne_b2,
                                              ne_g, ne_beta, p_h, p_hh);

    // conv layers: gather (half) + hgemm (fused postconv), ping-pong
    float* hinF = p_h;   __half* hinH = p_hh;
    float* houF = p_h2;  __half* houH = p_hh2;
    for (int l = 0; l < LL; l++) {
        gatherh_kernel<<<WB, 256>>>(hinH);
        hgemm_kernel<<<MB, 512, HG_DSM>>>(p_Abufh, KPAD, NN, KPAD,
                                          p_Wpackh + (long)l * HH * KPAD, KPAD,
                                          convG + l * HH, convBeta + l * HH,
                                          lnG + l * HH, lnB + l * HH,
                                          hinF, houF, houH);
        float* tf = hinF; hinF = houF; houF = tf;
        __half* th = hinH; hinH = houH; houH = th;
    }
    // final h is in g_h / g_hh

    // attention pooling
    pgate_kernel<<<MB, 256, PG_DSM>>>(p_hh, p_pgW1th, pgb1, pgW2, pgb2);
    expwsum_kernel<<<NB, 256>>>();

    // heads
    heads_kernel<<<1, 256>>>(clW1, clb1, clW2, clb2, prW1, prb1, prW2, prb2, out);
}

// round 17
// speedup vs baseline: 1.1656x; 1.1036x over previous
#include <cuda_runtime.h>
#include <cuda_fp16.h>
#include <math.h>
#include <stdint.h>

#define NN 50000
#define EE 1000000
#define NIN 1281
#define K1PAD 1312
#define HH 256
#define LL 4
#define KPAD 288            // 256 Hsum + 3 sh + 16 radial + 1 deg + 12 zero pad

// ---------------- scratch ----------------
__device__ __align__(256) __half g_hh[NN * HH];        // h half (ping)
__device__ __align__(256) __half g_hh2[NN * HH];       // h half (pong)
__device__ __align__(256) __half g_Abufh[NN * KPAD];
__device__ float g_gate[NN];
__device__ int   g_deg[NN];
__device__ int   g_rowptr[NN + 1];
__device__ int   g_cursor[NN];
__device__ int   g_csrc[EE];
__device__ __align__(256) __half g_W1th[HH * K1PAD];
__device__ __align__(256) __half g_W2th[HH * HH];
__device__ __align__(256) __half g_pgW1th[64 * HH];
__device__ __align__(256) __half g_Wpackh[LL * HH * KPAD];
__device__ float g_scal[4];
__device__ float g_Gvec[HH];
__device__ int   g_bsum[64];
__device__ unsigned g_amax;

// ---------------- helpers ----------------
__device__ __forceinline__ float warp_sum(float v) {
    #pragma unroll
    for (int o = 16; o; o >>= 1) v += __shfl_xor_sync(0xffffffffu, v, o);
    return v;
}
__device__ __forceinline__ float silu_f(float x) { return x / (1.f + expf(-x)); }
__device__ __forceinline__ uint32_t smem_u32(const void* p) {
    uint32_t a;
    asm("{ .reg .u64 t; cvta.to.shared.u64 t, %1; cvt.u32.u64 %0, t; }" : "=r"(a) : "l"(p));
    return a;
}
__device__ __forceinline__ unsigned fkey(float f) {
    unsigned u = __float_as_uint(f);
    return (u & 0x80000000u) ? ~u : (u | 0x80000000u);
}
__device__ __forceinline__ float funkey(unsigned k) {
    unsigned u = (k & 0x80000000u) ? (k & 0x7fffffffu) : ~k;
    return __uint_as_float(u);
}
#define CP_ASYNC16(dst, src) \
    asm volatile("cp.async.ca.shared.global [%0], [%1], 16;" :: "r"(dst), "l"(src))
#define CP_COMMIT() asm volatile("cp.async.commit_group;" ::: "memory")
#define CP_WAIT1()  asm volatile("cp.async.wait_group 1;" ::: "memory")
#define CP_WAIT0()  asm volatile("cp.async.wait_group 0;" ::: "memory")

__device__ __forceinline__ void addh8(float* a, uint4 v) {
    __half2 h0 = *reinterpret_cast<__half2*>(&v.x);
    __half2 h1 = *reinterpret_cast<__half2*>(&v.y);
    __half2 h2 = *reinterpret_cast<__half2*>(&v.z);
    __half2 h3 = *reinterpret_cast<__half2*>(&v.w);
    float2 f0 = __half22float2(h0);
    float2 f1 = __half22float2(h1);
    float2 f2 = __half22float2(h2);
    float2 f3 = __half22float2(h3);
    a[0] += f0.x; a[1] += f0.y; a[2] += f1.x; a[3] += f1.y;
    a[4] += f2.x; a[5] += f2.y; a[6] += f3.x; a[7] += f3.y;
}

__device__ __forceinline__ uint4 pack8h(const float* v) {
    uint4 r;
    __half2 h0 = __floats2half2_rn(v[0], v[1]);
    __half2 h1 = __floats2half2_rn(v[2], v[3]);
    __half2 h2 = __floats2half2_rn(v[4], v[5]);
    __half2 h3 = __floats2half2_rn(v[6], v[7]);
    r.x = *reinterpret_cast<unsigned*>(&h0);
    r.y = *reinterpret_cast<unsigned*>(&h1);
    r.z = *reinterpret_cast<unsigned*>(&h2);
    r.w = *reinterpret_cast<unsigned*>(&h3);
    return r;
}

// ---------------- setup ----------------
__global__ void zero_kernel() {
    int i = blockIdx.x * 256 + threadIdx.x;
    if (i < NN) { g_deg[i] = 0; g_cursor[i] = 0; }
    if (i < HH) g_Gvec[i] = 0.f;
    if (i < 4) g_scal[i] = 0.f;
    if (i == 0) { g_rowptr[0] = 0; g_amax = 0u; }
}

__global__ void edge1_kernel(const int* __restrict__ ei) {
    int e = blockIdx.x * 256 + threadIdx.x;
    if (e >= EE) return;
    atomicAdd(&g_deg[ei[EE + e]], 1);
}

__global__ void scan1_kernel() {
    __shared__ int s[1024];
    int tid = threadIdx.x;
    int gid = blockIdx.x * 1024 + tid;
    int v = (gid < NN) ? g_deg[gid] : 0;
    s[tid] = v;
    __syncthreads();
    for (int off = 1; off < 1024; off <<= 1) {
        int t = (tid >= off) ? s[tid - off] : 0;
        __syncthreads();
        s[tid] += t;
        __syncthreads();
    }
    if (gid < NN) g_rowptr[gid + 1] = s[tid];
    if (tid == 1023) g_bsum[blockIdx.x] = s[1023];
}

__global__ void scan3b_kernel(int nb) {
    __shared__ int pref[64];
    int tid = threadIdx.x;
    if (tid < 64) pref[tid] = (tid < nb) ? g_bsum[tid] : 0;
    __syncthreads();
    for (int off = 1; off < 64; off <<= 1) {
        int t = (tid >= off && tid < 64) ? pref[tid - off] : 0;
        __syncthreads();
        if (tid < 64) pref[tid] += t;
        __syncthreads();
    }
    int gid = blockIdx.x * 256 + tid;
    if (gid < NN) {
        int b = gid >> 10;
        if (b > 0) g_rowptr[gid + 1] += pref[b - 1];
    }
}

__global__ void edge2_kernel(const int* __restrict__ ei) {
    int e = blockIdx.x * 256 + threadIdx.x;
    if (e >= EE) return;
    int s = ei[e];
    int d = ei[EE + e];
    int slot = atomicAdd(&g_cursor[d], 1);
    g_csrc[g_rowptr[d] + slot] = s;
}

// warp-per-node edge-feature aggregation
__global__ void ef_kernel(const float* __restrict__ pos) {
    int w = (blockIdx.x * 256 + threadIdx.x) >> 5;
    int lane = threadIdx.x & 31;
    if (w >= NN) return;
    const float wd = 0.1953125f;
    const float cstep = 10.f / 15.f;
    float Ej[16];
    #pragma unroll
    for (int j = 0; j < 16; j++) {
        float c = cstep * (float)j;
        Ej[j] = expf(-wd * c * c);
    }
    float px = pos[3 * w + 0], py = pos[3 * w + 1], pz = pos[3 * w + 2];
    float shx = 0.f, shy = 0.f, shz = 0.f;
    float rad[16];
    #pragma unroll
    for (int j = 0; j < 16; j++) rad[j] = 0.f;
    int beg = g_rowptr[w], end = g_rowptr[w + 1];
    for (int e = beg + lane; e < end; e += 32) {
        int s = g_csrc[e];
        float rx = px - pos[3 * s + 0];
        float ry = py - pos[3 * s + 1];
        float rz = pz - pos[3 * s + 2];
        float dist = sqrtf(rx * rx + ry * ry + rz * rz);
        float inv = 1.f / fmaxf(dist, 1e-12f);
        shx += rx * inv; shy += ry * inv; shz += rz * inv;
        if (dist < 18.f) {
            float A = expf(-wd * dist * dist);
            float r1 = expf(2.f * wd * cstep * dist);
            float r2 = r1 * r1, r4 = r2 * r2, r8 = r4 * r4;
            float p[16];
            p[0] = A;         p[1] = A * r1;
            p[2] = p[0] * r2; p[3] = p[1] * r2;
            #pragma unroll
            for (int j = 0; j < 4; j++) p[4 + j] = p[j] * r4;
            #pragma unroll
            for (int j = 0; j < 8; j++) p[8 + j] = p[j] * r8;
            #pragma unroll
            for (int j = 0; j < 16; j++) rad[j] += p[j] * Ej[j];
        } else {
            #pragma unroll
            for (int j = 0; j < 16; j++) {
                float t = dist - cstep * (float)j;
                rad[j] += expf(-wd * t * t);
            }
        }
    }
    shx = warp_sum(shx);
    shy = warp_sum(shy);
    shz = warp_sum(shz);
    #pragma unroll
    for (int j = 0; j < 16; j++) rad[j] = warp_sum(rad[j]);
    if (lane == 0) {
        __half* ab = g_Abufh + (long)w * KPAD + 256;
        ab[0] = __float2half_rn(shx);
        ab[1] = __float2half_rn(shy);
        ab[2] = __float2half_rn(shz);
        #pragma unroll
        for (int j = 0; j < 16; j++) ab[3 + j] = __float2half_rn(rad[j]);
        ab[19] = __float2half_rn((float)(end - beg));
        #pragma unroll
        for (int j = 20; j < 32; j++) ab[j] = __float2half_rn(0.f);
    }
}

// merged weight preparation
#define PREP_S1 ((long)HH * K1PAD)
#define PREP_S2 (PREP_S1 + (long)HH * HH)
#define PREP_S3 (PREP_S2 + 64L * HH)
#define PREP_S4 (PREP_S3 + (long)LL * HH * KPAD)
__global__ void prep_kernel(const float* __restrict__ ne_W1, const float* __restrict__ ne_W2,
                            const float* __restrict__ pgW1,
                            const float* __restrict__ convW, const float* __restrict__ convB) {
    long idx = (long)blockIdx.x * 256 + threadIdx.x;
    if (idx < PREP_S1) {
        int n = (int)(idx / K1PAD), k = (int)(idx % K1PAD);
        g_W1th[idx] = __float2half_rn((k < NIN) ? ne_W1[(long)k * HH + n] : 0.f);
    } else if (idx < PREP_S2) {
        long r = idx - PREP_S1;
        int n = (int)(r / HH), k = (int)(r % HH);
        g_W2th[r] = __float2half_rn(ne_W2[(long)k * HH + n]);
    } else if (idx < PREP_S3) {
        long r = idx - PREP_S2;
        int n = (int)(r / HH), k = (int)(r % HH);
        g_pgW1th[r] = __float2half_rn(pgW1[(long)k * 64 + n]);
    } else if (idx < PREP_S4) {
        long r = idx - PREP_S3;
        int l = (int)(r / (HH * KPAD));
        int rem = (int)(r % (HH * KPAD));
        int n = rem / KPAD, k = rem % KPAD;
        float v = 0.f;
        if (k < 275)       v = convW[((long)l * 275 + k) * HH + n];
        else if (k == 275) v = convB[l * HH + n];
        g_Wpackh[r] = __float2half_rn(v);
    }
}

// ---------------- shared GEMM constants ----------------
#define ASTH 40
#define STGH ((128 + 256) * ASTH)
#define EPI_ST 258
#define HG_DSM (128 * EPI_ST * 4)

// ================= fused node encoder (R13 structure; half-only output) =========
#define AT2_ST 264
#define B2_STG (256 * ASTH)
__global__ __launch_bounds__(512, 1)
void encoder_fused_kernel(const float* __restrict__ x,
                          const __half* __restrict__ W1t,
                          const float* __restrict__ b1,
                          const __half* __restrict__ W2t,
                          const float* __restrict__ b2,
                          const float* __restrict__ lnG, const float* __restrict__ lnB,
                          __half* __restrict__ houtH) {
    extern __shared__ float smf[];
    __half* sm = (__half*)smf;
    int t = threadIdx.x;
    int lane = t & 31, warp = t >> 5;
    int wr = warp >> 3;
    int wc = warp & 7;
    int rowBase = blockIdx.x * 128;
    uint32_t smb = smem_u32(sm);

    int aRow = t >> 2, aCq = t & 3;
    int aGr = rowBase + aRow;
    if (aGr >= NN) aGr = NN - 1;

    int kq = lane & 3;
    int kg = lane >> 2;

    float acc[4][4][4];
    #pragma unroll
    for (int mi = 0; mi < 4; mi++)
        #pragma unroll
        for (int ni = 0; ni < 4; ni++)
            #pragma unroll
            for (int q = 0; q < 4; q++) acc[mi][ni][q] = 0.f;

    // ---------- phase 1: K = NIN ----------
    {
        const int K = NIN;
        int nT = (K + 31) >> 5;
        auto load_B = [&](int i, int s) {
            int k0 = i << 5;
            uint32_t sbase = smb + (uint32_t)(s * STGH) * 2u;
            #pragma unroll
            for (int it = 0; it < 2; it++) {
                int c = it * 512 + t;
                int n = c >> 2, cq = c & 3;
                const __half* src = W1t + (long)n * K1PAD + k0 + cq * 8;
                uint32_t dst = sbase + (uint32_t)(128 * ASTH + n * ASTH + cq * 8) * 2u;
                CP_ASYNC16(dst, src);
            }
        };
        auto ldg_A = [&](int i, float* r) {
            int k0 = (i << 5) + aCq * 8;
            const float* src = x + (long)aGr * NIN + k0;
            #pragma unroll
            for (int j = 0; j < 8; j++)
                r[j] = (k0 + j < K) ? src[j] : 0.f;
        };
        auto sts_A = [&](int s, const float* r) {
            __half* dst = sm + s * STGH + aRow * ASTH + aCq * 8;
            *(uint4*)dst = pack8h(r);
        };

        {
            float r0[8];
            ldg_A(0, r0); sts_A(0, r0);
            ldg_A(1, r0); sts_A(1, r0);
        }
        load_B(0, 0);
        CP_COMMIT();
        load_B(1, 1);
        CP_COMMIT();

        for (int i = 0; i < nT; i++) {
            CP_WAIT1();
            __syncthreads();
            float aStage[8];
            bool doStage = (i + 2 < nT);
            if (doStage) {
                ldg_A(i + 2, aStage);
                load_B(i + 2, (i + 2) % 3);
            }
            CP_COMMIT();

            const __half* As = sm + (i % 3) * STGH;
            const __half* Bs = As + 128 * ASTH;
            #pragma unroll
            for (int ks = 0; ks < 2; ks++) {
                int ko = ks * 16;
                unsigned af[4][4], bf[4][2];
                #pragma unroll
                for (int mi = 0; mi < 4; mi++) {
                    int ar = wr * 64 + mi * 16 + kg;
                    af[mi][0] = *(const unsigned*)(As + ar * ASTH + ko + kq * 2);
                    af[mi][1] = *(const unsigned*)(As + (ar + 8) * ASTH + ko + kq * 2);
                    af[mi][2] = *(const unsigned*)(As + ar * ASTH + ko + kq * 2 + 8);
                    af[mi][3] = *(const unsigned*)(As + (ar + 8) * ASTH + ko + kq * 2 + 8);
                }
                #pragma unroll
                for (int ni = 0; ni < 4; ni++) {
                    int bn = wc * 32 + ni * 8 + kg;
                    bf[ni][0] = *(const unsigned*)(Bs + bn * ASTH + ko + kq * 2);
                    bf[ni][1] = *(const unsigned*)(Bs + bn * ASTH + ko + kq * 2 + 8);
                }
                #pragma unroll
                for (int mi = 0; mi < 4; mi++)
                    #pragma unroll
                    for (int ni = 0; ni < 4; ni++) {
                        asm volatile(
                            "mma.sync.aligned.m16n8k16.row.col.f32.f16.f16.f32 "
                            "{%0,%1,%2,%3}, {%4,%5,%6,%7}, {%8,%9}, {%0,%1,%2,%3};"
                            : "+f"(acc[mi][ni][0]), "+f"(acc[mi][ni][1]),
                              "+f"(acc[mi][ni][2]), "+f"(acc[mi][ni][3])
                            : "r"(af[mi][0]), "r"(af[mi][1]), "r"(af[mi][2]), "r"(af[mi][3]),
                              "r"(bf[ni][0]), "r"(bf[ni][1]));
                    }
            }
            if (doStage) sts_A((i + 2) % 3, aStage);
        }
    }

    // ---------- phase boundary ----------
    CP_WAIT0();
    __syncthreads();
    #pragma unroll
    for (int mi = 0; mi < 4; mi++) {
        #pragma unroll
        for (int ni = 0; ni < 4; ni++) {
            int rloc0 = wr * 64 + mi * 16 + kg;
            int c0 = wc * 32 + ni * 8 + kq * 2;
            #pragma unroll
            for (int half = 0; half < 2; half++) {
                int rl = rloc0 + half * 8;
                float v0 = silu_f(acc[mi][ni][half * 2 + 0] + b1[c0]);
                float v1 = silu_f(acc[mi][ni][half * 2 + 1] + b1[c0 + 1]);
                *(__half2*)(sm + rl * AT2_ST + c0) = __floats2half2_rn(v0, v1);
            }
        }
    }
    __syncthreads();

    #pragma unroll
    for (int mi = 0; mi < 4; mi++)
        #pragma unroll
        for (int ni = 0; ni < 4; ni++)
            #pragma unroll
            for (int q = 0; q < 4; q++) acc[mi][ni][q] = 0.f;

    // ---------- phase 2 ----------
    {
        const __half* At = sm;
        __half* B2 = sm + 128 * AT2_ST;
        uint32_t b2b = smem_u32(B2);
        auto load_B2 = [&](int i, int s) {
            int k0 = i << 5;
            uint32_t sbase = b2b + (uint32_t)(s * B2_STG) * 2u;
            #pragma unroll
            for (int it = 0; it < 2; it++) {
                int c = it * 512 + t;
                int n = c >> 2, cq = c & 3;
                const __half* src = W2t + (long)n * HH + k0 + cq * 8;
                uint32_t dst = sbase + (uint32_t)(n * ASTH + cq * 8) * 2u;
                CP_ASYNC16(dst, src);
            }
        };
        load_B2(0, 0);
        CP_COMMIT();
        load_B2(1, 1);
        CP_COMMIT();
        for (int i = 0; i < 8; i++) {
            CP_WAIT1();
            __syncthreads();
            if (i + 2 < 8) load_B2(i + 2, (i + 2) % 3);
            CP_COMMIT();
            int k0 = i << 5;
            const __half* Bs = B2 + (i % 3) * B2_STG;
            #pragma unroll
            for (int ks = 0; ks < 2; ks++) {
                int ko = ks * 16;
                unsigned af[4][4], bf[4][2];
                #pragma unroll
                for (int mi = 0; mi < 4; mi++) {
                    int ar = wr * 64 + mi * 16 + kg;
                    af[mi][0] = *(const unsigned*)(At + ar * AT2_ST + k0 + ko + kq * 2);
                    af[mi][1] = *(const unsigned*)(At + (ar + 8) * AT2_ST + k0 + ko + kq * 2);
                    af[mi][2] = *(const unsigned*)(At + ar * AT2_ST + k0 + ko + kq * 2 + 8);
                    af[mi][3] = *(const unsigned*)(At + (ar + 8) * AT2_ST + k0 + ko + kq * 2 + 8);
                }
                #pragma unroll
                for (int ni = 0; ni < 4; ni++) {
                    int bn = wc * 32 + ni * 8 + kg;
                    bf[ni][0] = *(const unsigned*)(Bs + bn * ASTH + ko + kq * 2);
                    bf[ni][1] = *(const unsigned*)(Bs + bn * ASTH + ko + kq * 2 + 8);
                }
                #pragma unroll
                for (int mi = 0; mi < 4; mi++)
                    #pragma unroll
                    for (int ni = 0; ni < 4; ni++) {
                        asm volatile(
                            "mma.sync.aligned.m16n8k16.row.col.f32.f16.f16.f32 "
                            "{%0,%1,%2,%3}, {%4,%5,%6,%7}, {%8,%9}, {%0,%1,%2,%3};"
                            : "+f"(acc[mi][ni][0]), "+f"(acc[mi][ni][1]),
                              "+f"(acc[mi][ni][2]), "+f"(acc[mi][ni][3])
                            : "r"(af[mi][0]), "r"(af[mi][1]), "r"(af[mi][2]), "r"(af[mi][3]),
                              "r"(bf[ni][0]), "r"(bf[ni][1]));
                    }
            }
        }
    }

    // ---------- LN epilogue (half output only) ----------
    CP_WAIT0();
    __syncthreads();
    #pragma unroll
    for (int mi = 0; mi < 4; mi++) {
        #pragma unroll
        for (int ni = 0; ni < 4; ni++) {
            int rloc0 = wr * 64 + mi * 16 + kg;
            int c0 = wc * 32 + ni * 8 + kq * 2;
            #pragma unroll
            for (int half = 0; half < 2; half++) {
                int rl = rloc0 + half * 8;
                #pragma unroll
                for (int q = 0; q < 2; q++) {
                    int c = c0 + q;
                    smf[rl * EPI_ST + c] = acc[mi][ni][half * 2 + q] + b2[c];
                }
            }
        }
    }
    __syncthreads();
    #pragma unroll
    for (int rr = 0; rr < 8; rr++) {
        int rl = rr * 16 + warp;
        int gr = rowBase + rl;
        if (gr >= NN) continue;
        float xv[8];
        #pragma unroll
        for (int i = 0; i < 8; i++) xv[i] = smf[rl * EPI_ST + lane + 32 * i];
        float s = 0.f;
        #pragma unroll
        for (int i = 0; i < 8; i++) s += xv[i];
        s = warp_sum(s);
        float m = s * (1.f / 256.f);
        float qv = 0.f;
        #pragma unroll
        for (int i = 0; i < 8; i++) { float d = xv[i] - m; qv += d * d; }
        qv = warp_sum(qv);
        float rs = rsqrtf(qv * (1.f / 256.f) + 1e-5f);
        __half* oh = houtH + (long)gr * HH;
        #pragma unroll
        for (int i = 0; i < 8; i++) {
            int c = lane + 32 * i;
            float y = (xv[i] - m) * rs * lnG[c] + lnB[c];
            oh[c] = __float2half_rn(y);
        }
    }
}

// ================= FP16 GEMM (conv layers): half-only residual stream ======
__global__ __launch_bounds__(512, 1)
void hgemm_kernel(const __half* __restrict__ A, int lda, int M, int K,
                  const __half* __restrict__ Bt, int ldb,
                  const float* __restrict__ p1, const float* __restrict__ p2,
                  const float* __restrict__ p3, const float* __restrict__ p4,
                  const __half* __restrict__ hinH, __half* __restrict__ houtH) {
    extern __shared__ float smf[];
    __half* sm = (__half*)smf;
    int t = threadIdx.x;
    int lane = t & 31, warp = t >> 5;
    int wr = warp >> 3;
    int wc = warp & 7;
    int rowBase = blockIdx.x * 128;
    uint32_t smb = smem_u32(sm);

    int nT = (K + 31) >> 5;
    int aRow = t >> 2, aCq = t & 3;
    int aGr = rowBase + aRow;
    if (aGr >= M) aGr = M - 1;

    float acc[4][4][4];
    #pragma unroll
    for (int mi = 0; mi < 4; mi++)
        #pragma unroll
        for (int ni = 0; ni < 4; ni++)
            #pragma unroll
            for (int q = 0; q < 4; q++) acc[mi][ni][q] = 0.f;

    auto load_stage = [&](int i, int s) {
        int k0 = i << 5;
        uint32_t sbase = smb + (uint32_t)(s * STGH) * 2u;
        {
            const __half* src = A + (long)aGr * lda + k0 + aCq * 8;
            uint32_t dst = sbase + (uint32_t)(aRow * ASTH + aCq * 8) * 2u;
            CP_ASYNC16(dst, src);
        }
        #pragma unroll
        for (int it = 0; it < 2; it++) {
            int c = it * 512 + t;
            int n = c >> 2, cq = c & 3;
            const __half* src = Bt + (long)n * ldb + k0 + cq * 8;
            uint32_t dst = sbase + (uint32_t)(128 * ASTH + n * ASTH + cq * 8) * 2u;
            CP_ASYNC16(dst, src);
        }
    };

    load_stage(0, 0);
    CP_COMMIT();
    if (nT > 1) load_stage(1, 1);
    CP_COMMIT();

    int kq = lane & 3;
    int kg = lane >> 2;

    for (int i = 0; i < nT; i++) {
        CP_WAIT1();
        __syncthreads();
        if (i + 2 < nT) load_stage(i + 2, (i + 2) % 3);
        CP_COMMIT();

        const __half* As = sm + (i % 3) * STGH;
        const __half* Bs = As + 128 * ASTH;
        #pragma unroll
        for (int ks = 0; ks < 2; ks++) {
            int ko = ks * 16;
            unsigned af[4][4], bf[4][2];
            #pragma unroll
            for (int mi = 0; mi < 4; mi++) {
                int ar = wr * 64 + mi * 16 + kg;
                af[mi][0] = *(const unsigned*)(As + ar * ASTH + ko + kq * 2);
                af[mi][1] = *(const unsigned*)(As + (ar + 8) * ASTH + ko + kq * 2);
                af[mi][2] = *(const unsigned*)(As + ar * ASTH + ko + kq * 2 + 8);
                af[mi][3] = *(const unsigned*)(As + (ar + 8) * ASTH + ko + kq * 2 + 8);
            }
            #pragma unroll
            for (int ni = 0; ni < 4; ni++) {
                int bn = wc * 32 + ni * 8 + kg;
                bf[ni][0] = *(const unsigned*)(Bs + bn * ASTH + ko + kq * 2);
                bf[ni][1] = *(const unsigned*)(Bs + bn * ASTH + ko + kq * 2 + 8);
            }
            #pragma unroll
            for (int mi = 0; mi < 4; mi++)
                #pragma unroll
                for (int ni = 0; ni < 4; ni++) {
                    asm volatile(
                        "mma.sync.aligned.m16n8k16.row.col.f32.f16.f16.f32 "
                        "{%0,%1,%2,%3}, {%4,%5,%6,%7}, {%8,%9}, {%0,%1,%2,%3};"
                        : "+f"(acc[mi][ni][0]), "+f"(acc[mi][ni][1]),
                          "+f"(acc[mi][ni][2]), "+f"(acc[mi][ni][3])
                        : "r"(af[mi][0]), "r"(af[mi][1]), "r"(af[mi][2]), "r"(af[mi][3]),
                          "r"(bf[ni][0]), "r"(bf[ni][1]));
                }
        }
    }

    // postconv epilogue (half residual stream)
    __syncthreads();
    #pragma unroll
    for (int mi = 0; mi < 4; mi++) {
        #pragma unroll
        for (int ni = 0; ni < 4; ni++) {
            int rloc0 = wr * 64 + mi * 16 + kg;
            int c0 = wc * 32 + ni * 8 + kq * 2;
            #pragma unroll
            for (int half = 0; half < 2; half++) {
                int rl = rloc0 + half * 8;
                #pragma unroll
                for (int q = 0; q < 2; q++) {
                    int c = c0 + q;
                    smf[rl * EPI_ST + c] = acc[mi][ni][half * 2 + q];
                }
            }
        }
    }
    __syncthreads();

    #pragma unroll
    for (int rr = 0; rr < 8; rr++) {
        int rl = rr * 16 + warp;
        int gr = rowBase + rl;
        if (gr >= M) continue;
        const __half* hp = hinH + (long)gr * HH;
        __half* oh = houtH + (long)gr * HH;
        float x[8];
        float s = 0.f;
        #pragma unroll
        for (int i = 0; i < 8; i++) {
            x[i] = silu_f(smf[rl * EPI_ST + lane + 32 * i]);
            s += x[i];
        }
        s = warp_sum(s);
        float m1 = s * (1.f / 256.f);
        float qv = 0.f;
        #pragma unroll
        for (int i = 0; i < 8; i++) { float d = x[i] - m1; qv += d * d; }
        qv = warp_sum(qv);
        float rs1 = rsqrtf(qv * (1.f / 256.f) + 1e-5f);
        float z[8];
        float s2 = 0.f;
        #pragma unroll
        for (int i = 0; i < 8; i++) {
            int c = lane + 32 * i;
            float y = (x[i] - m1) * rs1 * p1[c] + p2[c];
            float zz = __half2float(hp[c]) + y;
            z[i] = zz; s2 += zz;
        }
        s2 = warp_sum(s2);
        float m2 = s2 * (1.f / 256.f);
        float q2 = 0.f;
        #pragma unroll
        for (int i = 0; i < 8; i++) { float d = z[i] - m2; q2 += d * d; }
        q2 = warp_sum(q2);
        float rs2 = rsqrtf(q2 * (1.f / 256.f) + 1e-5f);
        #pragma unroll
        for (int i = 0; i < 8; i++) {
            int c = lane + 32 * i;
            float y = (z[i] - m2) * rs2 * p3[c] + p4[c];
            oh[c] = __float2half_rn(y);
        }
    }
}

// ---------------- gather (half source) ----------------
__global__ void gatherh_kernel(const __half* __restrict__ hinh) {
    int w = (blockIdx.x * 256 + threadIdx.x) >> 5;
    int lane = threadIdx.x & 31;
    if (w >= NN) return;
    float a[8], b[8];
    #pragma unroll
    for (int j = 0; j < 8; j++) { a[j] = 0.f; b[j] = 0.f; }
    const uint4* base = (const uint4*)hinh;
    int beg = g_rowptr[w], end = g_rowptr[w + 1];
    int e = beg;
    for (; e + 1 < end; e += 2) {
        int s0 = g_csrc[e], s1 = g_csrc[e + 1];
        uint4 v = base[(long)s0 * 32 + lane];
        uint4 u = base[(long)s1 * 32 + lane];
        addh8(a, v);
        addh8(b, u);
    }
    if (e < end) {
        uint4 v = base[(long)g_csrc[e] * 32 + lane];
        addh8(a, v);
    }
    float out[8];
    #pragma unroll
    for (int j = 0; j < 8; j++) out[j] = a[j] + b[j];
    *(uint4*)(g_Abufh + (long)w * KPAD + lane * 8) = pack8h(out);
}

// ================= pool gate GEMM (fp16) + fused gate dot + block max =================
#define PG_STG ((128 + 64) * ASTH)
#define PG_DSM (3 * PG_STG * 2)
__global__ __launch_bounds__(256, 2)
void pgate_kernel(const __half* __restrict__ hh, const __half* __restrict__ Bt,
                  const float* __restrict__ bias,
                  const float* __restrict__ pgW2, const float* __restrict__ pgb2) {
    extern __shared__ __half smh[];
    __shared__ float wmax[8];
    float* smf = (float*)smh;
    int t = threadIdx.x;
    int lane = t & 31, warp = t >> 5;
    int wr = warp >> 2;
    int wc = warp & 3;
    int rowBase = blockIdx.x * 128;
    uint32_t smb = smem_u32(smh);

    float acc[4][2][4];
    #pragma unroll
    for (int mi = 0; mi < 4; mi++)
        #pragma unroll
        for (int ni = 0; ni < 2; ni++)
            #pragma unroll
            for (int q = 0; q < 4; q++) acc[mi][ni][q] = 0.f;

    auto load_stage = [&](int i, int s) {
        int k0 = i << 5;
        uint32_t sbase = smb + (uint32_t)(s * PG_STG) * 2u;
        #pragma unroll
        for (int it = 0; it < 2; it++) {
            int c = it * 256 + t;
            int row = c >> 2, cq = c & 3;
            int gr = rowBase + row;
            if (gr >= NN) gr = NN - 1;
            const __half* src = hh + (long)gr * HH + k0 + cq * 8;
            uint32_t dst = sbase + (uint32_t)(row * ASTH + cq * 8) * 2u;
            CP_ASYNC16(dst, src);
        }
        {
            int n = t >> 2, cq = t & 3;
            const __half* src = Bt + (long)n * HH + k0 + cq * 8;
            uint32_t dst = sbase + (uint32_t)(128 * ASTH + n * ASTH + cq * 8) * 2u;
            CP_ASYNC16(dst, src);
        }
    };

    load_stage(0, 0);
    CP_COMMIT();
    load_stage(1, 1);
    CP_COMMIT();

    int kq = lane & 3;
    int kg = lane >> 2;

    for (int i = 0; i < 8; i++) {
        CP_WAIT1();
        __syncthreads();
        if (i + 2 < 8) load_stage(i + 2, (i + 2) % 3);
        CP_COMMIT();

        const __half* As = smh + (i % 3) * PG_STG;
        const __half* Bs = As + 128 * ASTH;
        #pragma unroll
        for (int ks = 0; ks < 2; ks++) {
            int ko = ks * 16;
            unsigned af[4][4], bf[2][2];
            #pragma unroll
            for (int mi = 0; mi < 4; mi++) {
                int ar = wr * 64 + mi * 16 + kg;
                af[mi][0] = *(const unsigned*)(As + ar * ASTH + ko + kq * 2);
                af[mi][1] = *(const unsigned*)(As + (ar + 8) * ASTH + ko + kq * 2);
                af[mi][2] = *(const unsigned*)(As + ar * ASTH + ko + kq * 2 + 8);
                af[mi][3] = *(const unsigned*)(As + (ar + 8) * ASTH + ko + kq * 2 + 8);
            }
            #pragma unroll
            for (int ni = 0; ni < 2; ni++) {
                int bn = wc * 16 + ni * 8 + kg;
                bf[ni][0] = *(const unsigned*)(Bs + bn * ASTH + ko + kq * 2);
                bf[ni][1] = *(const unsigned*)(Bs + bn * ASTH + ko + kq * 2 + 8);
            }
            #pragma unroll
            for (int mi = 0; mi < 4; mi++)
                #pragma unroll
                for (int ni = 0; ni < 2; ni++) {
                    asm volatile(
                        "mma.sync.aligned.m16n8k16.row.col.f32.f16.f16.f32 "
                        "{%0,%1,%2,%3}, {%4,%5,%6,%7}, {%8,%9}, {%0,%1,%2,%3};"
                        : "+f"(acc[mi][ni][0]), "+f"(acc[mi][ni][1]),
                          "+f"(acc[mi][ni][2]), "+f"(acc[mi][ni][3])
                        : "r"(af[mi][0]), "r"(af[mi][1]), "r"(af[mi][2]), "r"(af[mi][3]),
                          "r"(bf[ni][0]), "r"(bf[ni][1]));
                }
        }
    }

    CP_WAIT0();
    __syncthreads();
    #pragma unroll
    for (int mi = 0; mi < 4; mi++) {
        #pragma unroll
        for (int ni = 0; ni < 2; ni++) {
            int r0 = wr * 64 + mi * 16 + kg;
            int c0 = wc * 16 + ni * 8 + kq * 2;
            #pragma unroll
            for (int half = 0; half < 2; half++) {
                int rl = r0 + half * 8;
                #pragma unroll
                for (int q = 0; q < 2; q++) {
                    int c = c0 + q;
                    smf[rl * 64 + c] = silu_f(acc[mi][ni][half * 2 + q] + bias[c]);
                }
            }
        }
    }
    __syncthreads();
    float lmax = -1e30f;
    float w0 = pgW2[lane], w1 = pgW2[32 + lane];
    for (int rr = 0; rr < 16; rr++) {
        int rl = rr * 8 + warp;
        int gr = rowBase + rl;
        if (gr >= NN) continue;
        float v = smf[rl * 64 + lane] * w0 + smf[rl * 64 + 32 + lane] * w1;
        v = warp_sum(v);
        if (lane == 0) {
            float g = v + pgb2[0];
            g_gate[gr] = g;
            lmax = fmaxf(lmax, g);
        }
    }
    if (lane == 0) wmax[warp] = lmax;
    __syncthreads();
    if (t == 0) {
        float m = wmax[0];
        #pragma unroll
        for (int j = 1; j < 8; j++) m = fmaxf(m, wmax[j]);
        atomicMax(&g_amax, fkey(m));
    }
}

// ---------------- pooling tail (reads half h) ----------------
__global__ void expwsum_kernel(const __half* __restrict__ hh) {
    __shared__ float e[256];
    __shared__ float red[256];
    int tid = threadIdx.x;
    int n = blockIdx.x * 256 + tid;
    float M = funkey(g_amax);
    float ev = 0.f;
    if (n < NN) ev = expf(g_gate[n] - M);
    e[tid] = ev;
    red[tid] = ev;
    __syncthreads();
    for (int o = 128; o; o >>= 1) {
        if (tid < o) red[tid] += red[tid + o];
        __syncthreads();
    }
    if (tid == 0) atomicAdd(&g_scal[1], red[0]);
    float acc = 0.f;
    int n0 = blockIdx.x * 256;
    for (int i = 0; i < 256; i++) {
        int nn = n0 + i;
        if (nn >= NN) break;
        acc += e[i] * __half2float(hh[(long)nn * HH + tid]);
    }
    atomicAdd(&g_Gvec[tid], acc);
}

// ---------------- heads ----------------
__global__ void heads_kernel(const float* __restrict__ clW1, const float* __restrict__ clb1,
                             const float* __restrict__ clW2, const float* __restrict__ clb2,
                             const float* __restrict__ prW1, const float* __restrict__ prb1,
                             const float* __restrict__ prW2, const float* __restrict__ prb2,
                             float* __restrict__ out) {
    __shared__ float emb[256], c1[128], p1[256], pr[128];
    __shared__ float nrm;
    int t = threadIdx.x;
    float se = g_scal[1];
    float ev = g_Gvec[t] / se;
    emb[t] = ev;
    out[132 + t] = ev;
    __syncthreads();
    if (t < 128) {
        float a = 0.f;
        for (int k = 0; k < 256; k++) a += emb[k] * clW1[k * 128 + t];
        a += clb1[t];
        c1[t] = silu_f(a);
    }
    {
        float a = 0.f;
        for (int k = 0; k < 256; k++) a += emb[k] * prW1[k * 256 + t];
        a += prb1[t];
        p1[t] = silu_f(a);
    }
    __syncthreads();
    if (t < 4) {
        float a = 0.f;
        for (int k = 0; k < 128; k++) a += c1[k] * clW2[k * 4 + t];
        out[t] = a + clb2[t];
    }
    if (t < 128) {
        float a = 0.f;
        for (int k = 0; k < 256; k++) a += p1[k] * prW2[k * 128 + t];
        pr[t] = a + prb2[t];
    }
    __syncthreads();
    if (t == 0) {
        float s = 0.f;
        for (int k = 0; k < 128; k++) s += pr[k] * pr[k];
        nrm = fmaxf(sqrtf(s), 1e-12f);
    }
    __syncthreads();
    if (t < 128) out[4 + t] = pr[t] / nrm;
}

// ---------------- launch ----------------
extern "C" void kernel_launch(void* const* d_in, const int* in_sizes, int n_in,
                              void* d_out, int out_size) {
    const float* x       = (const float*)d_in[0];
    const float* pos     = (const float*)d_in[1];
    const int*   ei      = (const int*)d_in[2];
    const float* ne_W1   = (const float*)d_in[3];
    const float* ne_b1   = (const float*)d_in[4];
    const float* ne_W2   = (const float*)d_in[5];
    const float* ne_b2   = (const float*)d_in[6];
    const float* ne_g    = (const float*)d_in[7];
    const float* ne_beta = (const float*)d_in[8];
    const float* convW   = (const float*)d_in[9];
    const float* convB   = (const float*)d_in[10];
    const float* convG   = (const float*)d_in[11];
    const float* convBeta= (const float*)d_in[12];
    const float* lnG     = (const float*)d_in[13];
    const float* lnB     = (const float*)d_in[14];
    const float* pgW1    = (const float*)d_in[15];
    const float* pgb1    = (const float*)d_in[16];
    const float* pgW2    = (const float*)d_in[17];
    const float* pgb2    = (const float*)d_in[18];
    const float* clW1    = (const float*)d_in[19];
    const float* clb1    = (const float*)d_in[20];
    const float* clW2    = (const float*)d_in[21];
    const float* clb2    = (const float*)d_in[22];
    const float* prW1    = (const float*)d_in[23];
    const float* prb1    = (const float*)d_in[24];
    const float* prW2    = (const float*)d_in[25];
    const float* prb2    = (const float*)d_in[26];
    float* out = (float*)d_out;

    __half *p_hh, *p_hh2, *p_W1th, *p_W2th, *p_pgW1th, *p_Wpackh, *p_Abufh;
    cudaGetSymbolAddress((void**)&p_hh, g_hh);
    cudaGetSymbolAddress((void**)&p_hh2, g_hh2);
    cudaGetSymbolAddress((void**)&p_W1th, g_W1th);
    cudaGetSymbolAddress((void**)&p_W2th, g_W2th);
    cudaGetSymbolAddress((void**)&p_pgW1th, g_pgW1th);
    cudaGetSymbolAddress((void**)&p_Wpackh, g_Wpackh);
    cudaGetSymbolAddress((void**)&p_Abufh, g_Abufh);

    cudaFuncSetAttribute(encoder_fused_kernel, cudaFuncAttributeMaxDynamicSharedMemorySize, HG_DSM);
    cudaFuncSetAttribute(hgemm_kernel, cudaFuncAttributeMaxDynamicSharedMemorySize, HG_DSM);
    cudaFuncSetAttribute(pgate_kernel, cudaFuncAttributeMaxDynamicSharedMemorySize, PG_DSM);

    const int EB = (EE + 255) / 256;
    const int NB = (NN + 255) / 256;
    const int WB = (NN + 7) / 8;
    const int MB = (NN + 127) / 128;
    const int SB = (NN + 1023) / 1024;
    const int PB = (int)((PREP_S4 + 255) / 256);

    // setup
    zero_kernel<<<NB, 256>>>();
    edge1_kernel<<<EB, 256>>>(ei);
    scan1_kernel<<<SB, 1024>>>();
    scan3b_kernel<<<NB, 256>>>(SB);
    edge2_kernel<<<EB, 256>>>(ei);
    ef_kernel<<<WB, 256>>>(pos);
    prep_kernel<<<PB, 256>>>(ne_W1, ne_W2, pgW1, convW, convB);

    // fused node encoder -> hh half
    encoder_fused_kernel<<<MB, 512, HG_DSM>>>(x, p_W1th, ne_b1, p_W2th, ne_b2,
                                              ne_g, ne_beta, p_hh);

    // conv layers: gather (half) + hgemm (fused postconv, half residual), ping-pong
    __half* hinH = p_hh;
    __half* houH = p_hh2;
    for (int l = 0; l < LL; l++) {
        gatherh_kernel<<<WB, 256>>>(hinH);
        hgemm_kernel<<<MB, 512, HG_DSM>>>(p_Abufh, KPAD, NN, KPAD,
                                          p_Wpackh + (long)l * HH * KPAD, KPAD,
                                          convG + l * HH, convBeta + l * HH,
                                          lnG + l * HH, lnB + l * HH,
                                          hinH, houH);
        __half* th = hinH; hinH = houH; houH = th;
    }
    // final h is in g_hh (hinH == p_hh)

    // attention pooling
    pgate_kernel<<<MB, 256, PG_DSM>>>(p_hh, p_pgW1th, pgb1, pgW2, pgb2);
    expwsum_kernel<<<NB, 256>>>(p_hh);

    // heads
    heads_kernel<<<1, 256>>>(clW1, clb1, clW2, clb2, prW1, prb1, prW2, prb2, out);
}